// round 11
// baseline (speedup 1.0000x reference)
#include <cuda_runtime.h>
#include <math.h>

typedef unsigned long long ull;

namespace {
constexpr int kB = 2, kC = 20000, kH = 64, kM = 8, kE = 200000, kP = 3;
constexpr int kNR = kB * kE;  // 400000 = 3125 * 128
constexpr int kNC = kB * kC;  // 40000
constexpr int TILE = 128;
constexpr int TBM = 256;   // msg threads
constexpr int NTILE = 160; // node rows/block (250 blocks exact)
constexpr int TB = 512;    // node threads

// msg_kernel shared layout (float offsets)
constexpr int OFF_W1C = 0;      // 4*64 = 256
constexpr int OFF_W2 = 256;     // 4096
constexpr int OFF_WG = 4352;    // 4096 (W2@P1)
constexpr int OFF_P2 = 8448;    // 64
constexpr int OFF_B1 = 8512;    // 64
constexpr int OFF_B2 = 8576;    // 64
constexpr int OFF_GB = 8640;    // 64 (b2@P1 + pb1)
constexpr int OFF_HM = 8704;    // 128*68 = 8704 (H)
constexpr int OFF_INV = 17408;  // 128*4
constexpr int OFF_REL = 17920;  // 384
constexpr int OFF_WT = 18304;   // 128
constexpr int OFF_DST = 18432;  // 128
constexpr int OFF_FS = 18560;   // 128
constexpr int OFF_FD = 18688;   // 128
constexpr int MSG_SMEM_FLOATS = 18816;  // 75,264 B -> 3 blocks/SM

// node_kernel shared layout
constexpr int NOFF_U1 = 0;       // 8192
constexpr int NOFF_U2 = 8192;    // 4096
constexpr int NOFF_UB1 = 12288;  // 64
constexpr int NOFF_UB2 = 12352;  // 64
constexpr int NOFF_HM = 12416;   // 160*68 = 10880
constexpr int NOFF_IDG = 23296;  // 160
constexpr int NODE_SMEM_FLOATS = 23456;  // 93,824 B -> 2 blocks/SM
}  // namespace

// Scratch (static device globals)
__device__ float g_agg[kNC * kH];
__device__ float g_posupd[kNC * kP];
__device__ float g_npos[kNC * kM * 3];
__device__ float g_np2[kNC * kM];
__device__ float g_cent[kNC * 3];
__device__ unsigned g_mbits[kC];
__device__ float g_fw[(size_t)kNC * 128];  // [node][0:64]=f@W1a, [64:128]=f@W1b
__device__ float g_w2p1[64 * 64];          // W2 @ P1
__device__ float g_gb[64];                 // b2 @ P1 + pb1

// ---- packed f32x2 helpers ----
__device__ __forceinline__ ull dup2(float v) {
  ull r;
  asm("mov.b64 %0, {%1, %1};" : "=l"(r) : "f"(v));
  return r;
}
__device__ __forceinline__ ull pack2f(float a, float b) {
  ull r;
  asm("mov.b64 %0, {%1, %2};" : "=l"(r) : "f"(a), "f"(b));
  return r;
}
__device__ __forceinline__ void ffma2(ull& d, ull a, ull b) {
  asm("fma.rn.f32x2 %0, %1, %2, %0;" : "+l"(d) : "l"(a), "l"(b));
}
__device__ __forceinline__ void fma2_scale_bias(ull& d, ull a, ull b) {
  asm("fma.rn.f32x2 %0, %0, %1, %2;" : "+l"(d) : "l"(a), "l"(b));
}
__device__ __forceinline__ float2 unpack2(ull v) {
  float2 f;
  asm("mov.b64 {%0, %1}, %2;" : "=f"(f.x), "=f"(f.y) : "l"(v));
  return f;
}
__device__ __forceinline__ void red_add_v4(float* p, float a, float b, float c,
                                           float d) {
  asm volatile("red.global.add.v4.f32 [%0], {%1, %2, %3, %4};" ::"l"(p), "f"(a),
               "f"(b), "f"(c), "f"(d)
               : "memory");
}
// silu via single-MUFU tanh.approx
__device__ __forceinline__ float silu_f(float v) {
  float t;
  asm("tanh.approx.f32 %0, %1;" : "=f"(t) : "f"(0.5f * v));
  return 0.5f * v * (1.f + t);
}

// R-row x 4-col tile, 64 k-steps, W row-major [64][64] in smem
template <int R>
__device__ __forceinline__ void gemm64r(const float* const xp[R],
                                        const float* __restrict__ W, int cg,
                                        ull (*acc)[2]) {
#pragma unroll
  for (int g = 0; g < 16; g++) {
    float4 xv[R];
#pragma unroll
    for (int r = 0; r < R; r++) xv[r] = *(const float4*)(xp[r] + 4 * g);
#pragma unroll
    for (int kk = 0; kk < 4; kk++) {
      ulonglong2 w = *(const ulonglong2*)(W + (4 * g + kk) * 64 + cg * 4);
#pragma unroll
      for (int r = 0; r < R; r++) {
        ull d = dup2(((const float*)&xv[r])[kk]);
        ffma2(acc[r][0], d, w.x);
        ffma2(acc[r][1], d, w.y);
      }
    }
  }
}

__global__ void zero_kernel() {
  int i = blockIdx.x * blockDim.x + threadIdx.x;
  if (i < kNC * kH) g_agg[i] = 0.f;
  if (i < kNC * kP) g_posupd[i] = 0.f;
}

__global__ void prep_kernel(const float* __restrict__ positions,
                            const int* __restrict__ cni,
                            const float* __restrict__ mask) {
  int i = blockIdx.x * blockDim.x + threadIdx.x;
  if (i >= kNC) return;
  int b = i / kC, c = i - b * kC;
  float sx = 0.f, sy = 0.f, sz = 0.f, cnt = 0.f;
  unsigned bits = 0;
#pragma unroll
  for (int m = 0; m < kM; m++) {
    int idx = cni[c * kM + m];
    const float* p = positions + ((size_t)b * kC + idx) * kP;
    float x = p[0], y = p[1], z = p[2];
    g_npos[((size_t)i * kM + m) * 3 + 0] = x;
    g_npos[((size_t)i * kM + m) * 3 + 1] = y;
    g_npos[((size_t)i * kM + m) * 3 + 2] = z;
    g_np2[i * kM + m] = x * x + y * y + z * z;
    float mk = mask[c * kM + m];
    if (mk > 0.f) { bits |= (1u << m); sx += x; sy += y; sz += z; cnt += 1.f; }
  }
  float den = fmaxf(cnt, 1e-12f);
  g_cent[i * 3 + 0] = sx / den;
  g_cent[i * 3 + 1] = sy / den;
  g_cent[i * 3 + 2] = sz / den;
  if (b == 0) g_mbits[c] = bits;
}

// W2P1 = W2 @ P1, gb = b2 @ P1 + pb1
__global__ void __launch_bounds__(256) w2p1_kernel(
    const float* __restrict__ W2, const float* __restrict__ P1,
    const float* __restrict__ b2, const float* __restrict__ pb1) {
  __shared__ float sP1k[4096];
  int t = threadIdx.x;
  for (int i = t; i < 4096; i += 256) sP1k[i] = P1[i];
  __syncthreads();
  for (int e = t; e < 4096; e += 256) {
    int k = e >> 6, n = e & 63;
    float s = 0.f;
#pragma unroll 8
    for (int j = 0; j < 64; j++) s += W2[k * 64 + j] * sP1k[j * 64 + n];
    g_w2p1[e] = s;
  }
  if (t < 64) {
    float s = pb1[t];
#pragma unroll 8
    for (int j = 0; j < 64; j++) s += b2[j] * sP1k[j * 64 + t];
    g_gb[t] = s;
  }
}

// F[node] = [features@W1a | features@W1b]  (hoisted GEMM1 node terms)
// 256 threads/block -> ~19.5K regs/block -> 3 blocks/SM (was reg-limited to 1)
__global__ void __launch_bounds__(256) featw_kernel(
    const float* __restrict__ features, const float* __restrict__ W1) {
  __shared__ float sW[64 * 128];
  int tid = threadIdx.x;
  for (int i = tid; i < 64 * 128; i += 256) {
    int k = i >> 7, n = i & 127;
    sW[i] = (n < 64) ? W1[k * 64 + n] : W1[(64 + k) * 64 + (n - 64)];
  }
  __syncthreads();
  int rg = tid >> 5, cg = tid & 31;
  int row0 = blockIdx.x * 40 + rg * 5;
  ull acc[5][2];
#pragma unroll
  for (int r = 0; r < 5; r++) { acc[r][0] = 0ull; acc[r][1] = 0ull; }
  const float* xp[5];
#pragma unroll
  for (int r = 0; r < 5; r++) xp[r] = features + (size_t)(row0 + r) * kH;
#pragma unroll
  for (int g = 0; g < 16; g++) {
    float4 xv[5];
#pragma unroll
    for (int r = 0; r < 5; r++) xv[r] = *(const float4*)(xp[r] + 4 * g);
#pragma unroll
    for (int kk = 0; kk < 4; kk++) {
      ulonglong2 w = *(const ulonglong2*)(sW + (4 * g + kk) * 128 + cg * 4);
#pragma unroll
      for (int r = 0; r < 5; r++) {
        ull d = dup2(((const float*)&xv[r])[kk]);
        ffma2(acc[r][0], d, w.x);
        ffma2(acc[r][1], d, w.y);
      }
    }
  }
#pragma unroll
  for (int r = 0; r < 5; r++) {
    float2 v0 = unpack2(acc[r][0]);
    float2 v1 = unpack2(acc[r][1]);
    *(float4*)(g_fw + (size_t)(row0 + r) * 128 + cg * 4) =
        make_float4(v0.x, v0.y, v1.x, v1.y);
  }
}

__global__ void __launch_bounds__(TBM, 3) msg_kernel(
    const float* __restrict__ features, const float* __restrict__ positions,
    const int* __restrict__ ei,
    const float* __restrict__ W1, const float* __restrict__ b1,
    const float* __restrict__ W2, const float* __restrict__ b2,
    const float* __restrict__ P2, const float* __restrict__ pb2) {
  extern __shared__ float sm[];
  float* sW1c = sm + OFF_W1C;
  float* sW2 = sm + OFF_W2;
  float* sWG = sm + OFF_WG;
  float* sP2 = sm + OFF_P2;
  float* sb1 = sm + OFF_B1;
  float* sb2 = sm + OFF_B2;
  float* sGB = sm + OFF_GB;
  float* sHM = sm + OFF_HM;    // [128][68] H
  float* sInv = sm + OFF_INV;  // [128][4]
  float* sRel = sm + OFF_REL;
  float* sWt = sm + OFF_WT;
  int* sDst = (int*)(sm + OFF_DST);
  int* sFs = (int*)(sm + OFF_FS);
  int* sFd = (int*)(sm + OFF_FD);

  int tid = threadIdx.x;
  for (int i = tid; i < 256; i += TBM) sW1c[i] = W1[128 * 64 + i];
  for (int i = tid; i < 64 * 64; i += TBM) {
    sW2[i] = W2[i];
    sWG[i] = g_w2p1[i];
  }
  if (tid < 64) {
    sP2[tid] = P2[tid];
    sb1[tid] = b1[tid];
    sb2[tid] = b2[tid];
    sGB[tid] = g_gb[tid];
  }
  float pb2v = pb2[0];

  // ---- gather (node indices + rel) ----
  if (tid < TILE) {
    int gr = blockIdx.x * TILE + tid;
    int b = gr / kE, e = gr - b * kE;
    int src = ei[e], dst = ei[kE + e];
    int is = b * kC + src, id = b * kC + dst;
    sFs[tid] = is;
    sFd[tid] = id;
    sDst[tid] = id;
    const float* ps = positions + (size_t)is * kP;
    const float* pd = positions + (size_t)id * kP;
    sRel[tid * 3 + 0] = ps[0] - pd[0];
    sRel[tid * 3 + 1] = ps[1] - pd[1];
    sRel[tid * 3 + 2] = ps[2] - pd[2];
  }
  __syncthreads();

  // ---- fused invariants: 2 threads per row ----
  {
    int row = tid >> 1, half = tid & 1;
    int is = sFs[row], id = sFd[row];
    unsigned mx = g_mbits[is >= kC ? is - kC : is];
    unsigned my = g_mbits[id >= kC ? id - kC : id];
    float dp[24], dp2[8];
    {
      const float4* a = (const float4*)(g_npos + (size_t)id * 24);
#pragma unroll
      for (int q = 0; q < 6; q++) ((float4*)dp)[q] = a[q];
      const float4* d2 = (const float4*)(g_np2 + (size_t)id * 8);
      ((float4*)dp2)[0] = d2[0];
      ((float4*)dp2)[1] = d2[1];
    }
    float sp[12], sp2[4];
    {
      const float4* a = (const float4*)(g_npos + (size_t)is * 24 + half * 12);
#pragma unroll
      for (int q = 0; q < 3; q++) ((float4*)sp)[q] = a[q];
      ((float4*)sp2)[0] = *(const float4*)(g_np2 + (size_t)is * 8 + half * 4);
    }
    float colmin[8];
#pragma unroll
    for (int n = 0; n < 8; n++) colmin[n] = 3.4e38f;
    float pairwise = 0.f, hxy = 0.f;
    unsigned mxs = mx >> (half * 4);
#pragma unroll
    for (int m = 0; m < 4; m++) {
      if ((mxs >> m) & 1) {
        float rowmin = 3.4e38f;
        float ax = sp[m * 3], ay = sp[m * 3 + 1], az = sp[m * 3 + 2],
              a2 = sp2[m];
#pragma unroll
        for (int n = 0; n < 8; n++) {
          if ((my >> n) & 1) {
            float s = a2 + dp2[n] -
                      2.f * (ax * dp[n * 3] + ay * dp[n * 3 + 1] +
                             az * dp[n * 3 + 2]);
            float d = sqrtf(fmaxf(s, 0.f) + 1e-12f);
            pairwise += d;
            rowmin = fminf(rowmin, d);
            colmin[n] = fminf(colmin[n], d);
          }
        }
        hxy = fmaxf(hxy, rowmin);
      }
    }
    pairwise += __shfl_xor_sync(0xffffffffu, pairwise, 1);
    hxy = fmaxf(hxy, __shfl_xor_sync(0xffffffffu, hxy, 1));
#pragma unroll
    for (int n = 0; n < 8; n++)
      colmin[n] = fminf(colmin[n], __shfl_xor_sync(0xffffffffu, colmin[n], 1));
    if (half == 0) {
      float hyx = 0.f;
#pragma unroll
      for (int n = 0; n < 8; n++)
        if ((my >> n) & 1) hyx = fmaxf(hyx, colmin[n]);
      float haus = fmaxf(hxy, hyx);
      float c0 = g_cent[is * 3 + 0] - g_cent[id * 3 + 0];
      float c1 = g_cent[is * 3 + 1] - g_cent[id * 3 + 1];
      float c2 = g_cent[is * 3 + 2] - g_cent[id * 3 + 2];
      float centroid = sqrtf(c0 * c0 + c1 * c1 + c2 * c2);
      float r0 = sRel[row * 3 + 0], r1 = sRel[row * 3 + 1],
            r2 = sRel[row * 3 + 2];
      float dist = sqrtf(r0 * r0 + r1 * r1 + r2 * r2);
      ((float4*)sInv)[row] = make_float4(dist, pairwise, centroid, haus);
    }
  }
  __syncthreads();

  int rg = tid >> 4, cg = tid & 15;
  int row0 = rg * 8;

  // ---- GEMM1 (hoisted): H = silu(b1 + F[src] + F[dst] + inv@W1c) ----
  {
    ull acc[8][2];
    float bb0 = sb1[cg * 4 + 0], bb1 = sb1[cg * 4 + 1];
    float bb2 = sb1[cg * 4 + 2], bb3 = sb1[cg * 4 + 3];
#pragma unroll
    for (int r = 0; r < 8; r++) {
      int is = sFs[row0 + r], id = sFd[row0 + r];
      float4 fs = *(const float4*)(g_fw + (size_t)is * 128 + cg * 4);
      float4 fd = *(const float4*)(g_fw + (size_t)id * 128 + 64 + cg * 4);
      acc[r][0] = pack2f(bb0 + fs.x + fd.x, bb1 + fs.y + fd.y);
      acc[r][1] = pack2f(bb2 + fs.z + fd.z, bb3 + fs.w + fd.w);
    }
    float4 iv[8];
#pragma unroll
    for (int r = 0; r < 8; r++) iv[r] = ((const float4*)sInv)[row0 + r];
#pragma unroll
    for (int kk = 0; kk < 4; kk++) {
      ulonglong2 w = *(const ulonglong2*)(sW1c + kk * 64 + cg * 4);
#pragma unroll
      for (int r = 0; r < 8; r++) {
        ull d = dup2(((const float*)&iv[r])[kk]);
        ffma2(acc[r][0], d, w.x);
        ffma2(acc[r][1], d, w.y);
      }
    }
#pragma unroll
    for (int i = 0; i < 8; i++)
#pragma unroll
      for (int p = 0; p < 2; p++) {
        float2 h = unpack2(acc[i][p]);
        h.x = silu_f(h.x);
        h.y = silu_f(h.y);
        *(float2*)(sHM + (row0 + i) * 68 + cg * 4 + 2 * p) = h;
      }
  }
  __syncthreads();

  // ---- pass A: Msg = H@W2 + b2, scatter straight from registers ----
  {
    ull acc[8][2];
#pragma unroll
    for (int i = 0; i < 8; i++) {
      acc[i][0] = *(const ull*)(sb2 + cg * 4 + 0);
      acc[i][1] = *(const ull*)(sb2 + cg * 4 + 2);
    }
    const float* xp[8];
#pragma unroll
    for (int r = 0; r < 8; r++) xp[r] = sHM + (row0 + r) * 68;
    gemm64r<8>(xp, sW2, cg, acc);
#pragma unroll
    for (int r = 0; r < 8; r++) {
      float2 m0 = unpack2(acc[r][0]);
      float2 m1 = unpack2(acc[r][1]);
      red_add_v4(g_agg + (size_t)sDst[row0 + r] * kH + cg * 4, m0.x, m0.y,
                 m1.x, m1.y);
    }
  }

  // ---- pass B: G = H@W2P1 + gb, gate (H unchanged, no sync needed) ----
  {
    ull acc[8][2];
#pragma unroll
    for (int i = 0; i < 8; i++) {
      acc[i][0] = *(const ull*)(sGB + cg * 4 + 0);
      acc[i][1] = *(const ull*)(sGB + cg * 4 + 2);
    }
    const float* xp[8];
#pragma unroll
    for (int r = 0; r < 8; r++) xp[r] = sHM + (row0 + r) * 68;
    gemm64r<8>(xp, sWG, cg, acc);
    float p2a = sP2[cg * 4 + 0], p2b = sP2[cg * 4 + 1];
    float p2c = sP2[cg * 4 + 2], p2d = sP2[cg * 4 + 3];
#pragma unroll
    for (int r = 0; r < 8; r++) {
      float2 g0 = unpack2(acc[r][0]);
      float2 g1 = unpack2(acc[r][1]);
      float part = silu_f(g0.x) * p2a;
      part = fmaf(silu_f(g0.y), p2b, part);
      part = fmaf(silu_f(g1.x), p2c, part);
      part = fmaf(silu_f(g1.y), p2d, part);
      part += __shfl_xor_sync(0xffffffffu, part, 1);
      part += __shfl_xor_sync(0xffffffffu, part, 2);
      part += __shfl_xor_sync(0xffffffffu, part, 4);
      part += __shfl_xor_sync(0xffffffffu, part, 8);
      if (cg == 0) sWt[row0 + r] = tanhf(part + pb2v);
    }
  }
  __syncthreads();
  if (tid < TILE) {
    float w = sWt[tid];
    float* pp = g_posupd + (size_t)sDst[tid] * kP;
    atomicAdd(pp + 0, w * sRel[tid * 3 + 0]);
    atomicAdd(pp + 1, w * sRel[tid * 3 + 1]);
    atomicAdd(pp + 2, w * sRel[tid * 3 + 2]);
  }
}

__global__ void __launch_bounds__(TB, 2) node_kernel(
    const float* __restrict__ features, const float* __restrict__ degree,
    const float* __restrict__ U1, const float* __restrict__ ub1,
    const float* __restrict__ U2, const float* __restrict__ ub2,
    float* __restrict__ out_feat) {
  extern __shared__ float smf[];
  float* sU1 = smf + NOFF_U1;
  float* sU2 = smf + NOFF_U2;
  float* sub1 = smf + NOFF_UB1;
  float* sub2 = smf + NOFF_UB2;
  float* sHM = smf + NOFF_HM;  // [160][68]
  float* sInvD = smf + NOFF_IDG;

  int tid = threadIdx.x;
  for (int i = tid; i < 128 * 64; i += TB) sU1[i] = U1[i];
  for (int i = tid; i < 64 * 64; i += TB) sU2[i] = U2[i];
  if (tid < 64) { sub1[tid] = ub1[tid]; sub2[tid] = ub2[tid]; }

  if (tid < NTILE) {
    int gr = blockIdx.x * NTILE + tid;
    int c = gr % kC;
    sInvD[tid] = 1.f / fmaxf(degree[c], 1.f);
  }
  __syncthreads();

  int rg = tid >> 4, cg = tid & 15;
  int row0 = rg * 5;
  int gr0 = blockIdx.x * NTILE + row0;

  ull acc[5][2];
#pragma unroll
  for (int i = 0; i < 5; i++) { acc[i][0] = 0ull; acc[i][1] = 0ull; }

  {
    const float* xp[5];
#pragma unroll
    for (int r = 0; r < 5; r++) xp[r] = g_agg + (size_t)(gr0 + r) * kH;
    gemm64r<5>(xp, sU1 + 64 * 64, cg, acc);
  }
  {
    ull bias0 = *(const ull*)(sub1 + cg * 4 + 0);
    ull bias1 = *(const ull*)(sub1 + cg * 4 + 2);
#pragma unroll
    for (int i = 0; i < 5; i++) {
      ull dv = dup2(sInvD[row0 + i]);
      fma2_scale_bias(acc[i][0], dv, bias0);
      fma2_scale_bias(acc[i][1], dv, bias1);
    }
  }
  {
    const float* xp[5];
#pragma unroll
    for (int r = 0; r < 5; r++) xp[r] = features + (size_t)(gr0 + r) * kH;
    gemm64r<5>(xp, sU1, cg, acc);
  }
#pragma unroll
  for (int i = 0; i < 5; i++)
#pragma unroll
    for (int p = 0; p < 2; p++) {
      float2 h = unpack2(acc[i][p]);
      h.x = silu_f(h.x);
      h.y = silu_f(h.y);
      *(float2*)(sHM + (row0 + i) * 68 + cg * 4 + 2 * p) = h;
    }
  __syncthreads();

#pragma unroll
  for (int i = 0; i < 5; i++) {
    acc[i][0] = *(const ull*)(sub2 + cg * 4 + 0);
    acc[i][1] = *(const ull*)(sub2 + cg * 4 + 2);
  }
  {
    const float* xp[5];
#pragma unroll
    for (int r = 0; r < 5; r++) xp[r] = sHM + (row0 + r) * 68;
    gemm64r<5>(xp, sU2, cg, acc);
  }
#pragma unroll
  for (int i = 0; i < 5; i++) {
    int g2 = gr0 + i;
    const float4 f = ((const float4*)(features + (size_t)g2 * kH))[cg];
    float2 v0 = unpack2(acc[i][0]);
    float2 v1 = unpack2(acc[i][1]);
    float4 o;
    o.x = f.x + v0.x;
    o.y = f.y + v0.y;
    o.z = f.z + v1.x;
    o.w = f.w + v1.y;
    ((float4*)(out_feat + (size_t)g2 * kH))[cg] = o;
  }
}

__global__ void pos_kernel(const float* __restrict__ positions,
                           float* __restrict__ out_pos) {
  int i = blockIdx.x * blockDim.x + threadIdx.x;
  if (i < kNC * kP) out_pos[i] = positions[i] + g_posupd[i];
}

extern "C" void kernel_launch(void* const* d_in, const int* in_sizes, int n_in,
                              void* d_out, int out_size) {
  const float* features = (const float*)d_in[0];
  const float* positions = (const float*)d_in[1];
  const int* edge_index = (const int*)d_in[2];
  const float* degree = (const float*)d_in[3];
  const int* cni = (const int*)d_in[4];
  const float* mask = (const float*)d_in[5];
  const float* W1 = (const float*)d_in[6];
  const float* b1 = (const float*)d_in[7];
  const float* W2 = (const float*)d_in[8];
  const float* b2 = (const float*)d_in[9];
  const float* P1 = (const float*)d_in[10];
  const float* pb1 = (const float*)d_in[11];
  const float* P2 = (const float*)d_in[12];
  const float* pb2 = (const float*)d_in[13];
  const float* U1 = (const float*)d_in[14];
  const float* ub1 = (const float*)d_in[15];
  const float* U2 = (const float*)d_in[16];
  const float* ub2 = (const float*)d_in[17];

  float* out_feat = (float*)d_out;
  float* out_pos = out_feat + (size_t)kNC * kH;

  size_t msg_smem = (size_t)MSG_SMEM_FLOATS * sizeof(float);    // 75,264 B
  size_t node_smem = (size_t)NODE_SMEM_FLOATS * sizeof(float);  // 93,824 B
  cudaFuncSetAttribute(msg_kernel, cudaFuncAttributeMaxDynamicSharedMemorySize,
                       (int)msg_smem);
  cudaFuncSetAttribute(node_kernel, cudaFuncAttributeMaxDynamicSharedMemorySize,
                       (int)node_smem);

  zero_kernel<<<(kNC * kH + 255) / 256, 256>>>();
  prep_kernel<<<(kNC + 255) / 256, 256>>>(positions, cni, mask);
  w2p1_kernel<<<1, 256>>>(W2, P1, b2, pb1);
  featw_kernel<<<kNC / 40, 256>>>(features, W1);
  msg_kernel<<<kNR / TILE, TBM, msg_smem>>>(features, positions, edge_index, W1,
                                            b1, W2, b2, P2, pb2);
  node_kernel<<<kNC / NTILE, TB, node_smem>>>(features, degree, U1, ub1, U2,
                                              ub2, out_feat);
  pos_kernel<<<(kNC * kP + 255) / 256, 256>>>(positions, out_pos);
}

// round 12
// speedup vs baseline: 3.7288x; 3.7288x over previous
#include <cuda_runtime.h>
#include <math.h>

typedef unsigned long long ull;

namespace {
constexpr int kB = 2, kC = 20000, kH = 64, kM = 8, kE = 200000, kP = 3;
constexpr int kNR = kB * kE;  // 400000 = 3125 * 128
constexpr int kNC = kB * kC;  // 40000
constexpr int TILE = 128;
constexpr int TBM = 256;   // msg threads
constexpr int NTILE = 160; // node rows/block (250 blocks exact)
constexpr int TB = 512;    // node threads

// msg_kernel shared layout (float offsets)  [identical to R9]
constexpr int OFF_W1C = 0;      // 4*64 = 256
constexpr int OFF_W2 = 256;     // 4096
constexpr int OFF_P1 = 4352;    // 4096
constexpr int OFF_P2 = 8448;    // 64
constexpr int OFF_B1 = 8512;    // 64
constexpr int OFF_B2 = 8576;    // 64
constexpr int OFF_PB1 = 8640;   // 64
constexpr int OFF_HM = 8704;    // 128*68 = 8704 (H then Msg)
constexpr int OFF_INV = 17408;  // 128*4
constexpr int OFF_REL = 17920;  // 384
constexpr int OFF_WT = 18304;   // 128
constexpr int OFF_DST = 18432;  // 128
constexpr int OFF_FS = 18560;   // 128
constexpr int OFF_FD = 18688;   // 128
constexpr int MSG_SMEM_FLOATS = 18816;  // 75,264 B -> 3 blocks/SM

// node_kernel shared layout
constexpr int NOFF_U1 = 0;       // 8192
constexpr int NOFF_U2 = 8192;    // 4096
constexpr int NOFF_UB1 = 12288;  // 64
constexpr int NOFF_UB2 = 12352;  // 64
constexpr int NOFF_HM = 12416;   // 160*68 = 10880
constexpr int NOFF_IDG = 23296;  // 160
constexpr int NODE_SMEM_FLOATS = 23456;  // 93,824 B -> 2 blocks/SM
}  // namespace

// Scratch (static device globals)
__device__ float g_agg[kNC * kH];
__device__ float g_posupd[kNC * kP];
__device__ float g_npos[kNC * kM * 3];
__device__ float g_np2[kNC * kM];
__device__ float g_cent[kNC * 3];
__device__ unsigned g_mbits[kC];
__device__ float g_fw[(size_t)kNC * 128];  // [node][0:64]=f@W1a, [64:128]=f@W1b

// ---- packed f32x2 helpers ----
__device__ __forceinline__ ull dup2(float v) {
  ull r;
  asm("mov.b64 %0, {%1, %1};" : "=l"(r) : "f"(v));
  return r;
}
__device__ __forceinline__ ull pack2f(float a, float b) {
  ull r;
  asm("mov.b64 %0, {%1, %2};" : "=l"(r) : "f"(a), "f"(b));
  return r;
}
__device__ __forceinline__ void ffma2(ull& d, ull a, ull b) {
  asm("fma.rn.f32x2 %0, %1, %2, %0;" : "+l"(d) : "l"(a), "l"(b));
}
__device__ __forceinline__ void fma2_scale_bias(ull& d, ull a, ull b) {
  asm("fma.rn.f32x2 %0, %0, %1, %2;" : "+l"(d) : "l"(a), "l"(b));
}
__device__ __forceinline__ float2 unpack2(ull v) {
  float2 f;
  asm("mov.b64 {%0, %1}, %2;" : "=f"(f.x), "=f"(f.y) : "l"(v));
  return f;
}
__device__ __forceinline__ void red_add_v4(float* p, float a, float b, float c,
                                           float d) {
  asm volatile("red.global.add.v4.f32 [%0], {%1, %2, %3, %4};" ::"l"(p), "f"(a),
               "f"(b), "f"(c), "f"(d)
               : "memory");
}
// silu via single-MUFU tanh.approx
__device__ __forceinline__ float silu_f(float v) {
  float t;
  asm("tanh.approx.f32 %0, %1;" : "=f"(t) : "f"(0.5f * v));
  return 0.5f * v * (1.f + t);
}

// R-row x 4-col tile, 64 k-steps, W row-major [64][64] in smem
template <int R>
__device__ __forceinline__ void gemm64r(const float* const xp[R],
                                        const float* __restrict__ W, int cg,
                                        ull (*acc)[2]) {
#pragma unroll
  for (int g = 0; g < 16; g++) {
    float4 xv[R];
#pragma unroll
    for (int r = 0; r < R; r++) xv[r] = *(const float4*)(xp[r] + 4 * g);
#pragma unroll
    for (int kk = 0; kk < 4; kk++) {
      ulonglong2 w = *(const ulonglong2*)(W + (4 * g + kk) * 64 + cg * 4);
#pragma unroll
      for (int r = 0; r < R; r++) {
        ull d = dup2(((const float*)&xv[r])[kk]);
        ffma2(acc[r][0], d, w.x);
        ffma2(acc[r][1], d, w.y);
      }
    }
  }
}

__global__ void zero_kernel() {
  int i = blockIdx.x * blockDim.x + threadIdx.x;
  if (i < kNC * kH) g_agg[i] = 0.f;
  if (i < kNC * kP) g_posupd[i] = 0.f;
}

__global__ void prep_kernel(const float* __restrict__ positions,
                            const int* __restrict__ cni,
                            const float* __restrict__ mask) {
  int i = blockIdx.x * blockDim.x + threadIdx.x;
  if (i >= kNC) return;
  int b = i / kC, c = i - b * kC;
  float sx = 0.f, sy = 0.f, sz = 0.f, cnt = 0.f;
  unsigned bits = 0;
#pragma unroll
  for (int m = 0; m < kM; m++) {
    int idx = cni[c * kM + m];
    const float* p = positions + ((size_t)b * kC + idx) * kP;
    float x = p[0], y = p[1], z = p[2];
    g_npos[((size_t)i * kM + m) * 3 + 0] = x;
    g_npos[((size_t)i * kM + m) * 3 + 1] = y;
    g_npos[((size_t)i * kM + m) * 3 + 2] = z;
    g_np2[i * kM + m] = x * x + y * y + z * z;
    float mk = mask[c * kM + m];
    if (mk > 0.f) { bits |= (1u << m); sx += x; sy += y; sz += z; cnt += 1.f; }
  }
  float den = fmaxf(cnt, 1e-12f);
  g_cent[i * 3 + 0] = sx / den;
  g_cent[i * 3 + 1] = sy / den;
  g_cent[i * 3 + 2] = sz / den;
  if (b == 0) g_mbits[c] = bits;
}

// F[node] = [features@W1a | features@W1b]  (hoisted GEMM1 node terms)
// 256 threads/block -> 3 blocks/SM (validated: 31us vs 36us at 512 threads)
__global__ void __launch_bounds__(256) featw_kernel(
    const float* __restrict__ features, const float* __restrict__ W1) {
  __shared__ float sW[64 * 128];
  int tid = threadIdx.x;
  for (int i = tid; i < 64 * 128; i += 256) {
    int k = i >> 7, n = i & 127;
    sW[i] = (n < 64) ? W1[k * 64 + n] : W1[(64 + k) * 64 + (n - 64)];
  }
  __syncthreads();
  int rg = tid >> 5, cg = tid & 31;
  int row0 = blockIdx.x * 40 + rg * 5;
  ull acc[5][2];
#pragma unroll
  for (int r = 0; r < 5; r++) { acc[r][0] = 0ull; acc[r][1] = 0ull; }
  const float* xp[5];
#pragma unroll
  for (int r = 0; r < 5; r++) xp[r] = features + (size_t)(row0 + r) * kH;
#pragma unroll
  for (int g = 0; g < 16; g++) {
    float4 xv[5];
#pragma unroll
    for (int r = 0; r < 5; r++) xv[r] = *(const float4*)(xp[r] + 4 * g);
#pragma unroll
    for (int kk = 0; kk < 4; kk++) {
      ulonglong2 w = *(const ulonglong2*)(sW + (4 * g + kk) * 128 + cg * 4);
#pragma unroll
      for (int r = 0; r < 5; r++) {
        ull d = dup2(((const float*)&xv[r])[kk]);
        ffma2(acc[r][0], d, w.x);
        ffma2(acc[r][1], d, w.y);
      }
    }
  }
#pragma unroll
  for (int r = 0; r < 5; r++) {
    float2 v0 = unpack2(acc[r][0]);
    float2 v1 = unpack2(acc[r][1]);
    *(float4*)(g_fw + (size_t)(row0 + r) * 128 + cg * 4) =
        make_float4(v0.x, v0.y, v1.x, v1.y);
  }
}

// msg_kernel: exact R9 structure (known 242us, spill-free at occupancy 3)
__global__ void __launch_bounds__(TBM, 3) msg_kernel(
    const float* __restrict__ features, const float* __restrict__ positions,
    const int* __restrict__ ei,
    const float* __restrict__ W1, const float* __restrict__ b1,
    const float* __restrict__ W2, const float* __restrict__ b2,
    const float* __restrict__ P1, const float* __restrict__ pb1,
    const float* __restrict__ P2, const float* __restrict__ pb2) {
  extern __shared__ float sm[];
  float* sW1c = sm + OFF_W1C;
  float* sW2 = sm + OFF_W2;
  float* sP1 = sm + OFF_P1;
  float* sP2 = sm + OFF_P2;
  float* sb1 = sm + OFF_B1;
  float* sb2 = sm + OFF_B2;
  float* spb1 = sm + OFF_PB1;
  float* sHM = sm + OFF_HM;    // [128][68] H, then Msg
  float* sInv = sm + OFF_INV;  // [128][4]
  float* sRel = sm + OFF_REL;
  float* sWt = sm + OFF_WT;
  int* sDst = (int*)(sm + OFF_DST);
  int* sFs = (int*)(sm + OFF_FS);
  int* sFd = (int*)(sm + OFF_FD);

  int tid = threadIdx.x;
  for (int i = tid; i < 256; i += TBM) sW1c[i] = W1[128 * 64 + i];
  for (int i = tid; i < 64 * 64; i += TBM) { sW2[i] = W2[i]; sP1[i] = P1[i]; }
  if (tid < 64) { sP2[tid] = P2[tid]; sb1[tid] = b1[tid]; sb2[tid] = b2[tid]; spb1[tid] = pb1[tid]; }
  float pb2v = pb2[0];

  // ---- gather (node indices + rel) ----
  if (tid < TILE) {
    int gr = blockIdx.x * TILE + tid;
    int b = gr / kE, e = gr - b * kE;
    int src = ei[e], dst = ei[kE + e];
    int is = b * kC + src, id = b * kC + dst;
    sFs[tid] = is;
    sFd[tid] = id;
    sDst[tid] = id;
    const float* ps = positions + (size_t)is * kP;
    const float* pd = positions + (size_t)id * kP;
    sRel[tid * 3 + 0] = ps[0] - pd[0];
    sRel[tid * 3 + 1] = ps[1] - pd[1];
    sRel[tid * 3 + 2] = ps[2] - pd[2];
  }
  __syncthreads();

  // ---- fused invariants: 2 threads per row ----
  {
    int row = tid >> 1, half = tid & 1;
    int is = sFs[row], id = sFd[row];
    unsigned mx = g_mbits[is >= kC ? is - kC : is];
    unsigned my = g_mbits[id >= kC ? id - kC : id];
    float dp[24], dp2[8];
    {
      const float4* a = (const float4*)(g_npos + (size_t)id * 24);
#pragma unroll
      for (int q = 0; q < 6; q++) ((float4*)dp)[q] = a[q];
      const float4* d2 = (const float4*)(g_np2 + (size_t)id * 8);
      ((float4*)dp2)[0] = d2[0];
      ((float4*)dp2)[1] = d2[1];
    }
    float sp[12], sp2[4];
    {
      const float4* a = (const float4*)(g_npos + (size_t)is * 24 + half * 12);
#pragma unroll
      for (int q = 0; q < 3; q++) ((float4*)sp)[q] = a[q];
      ((float4*)sp2)[0] = *(const float4*)(g_np2 + (size_t)is * 8 + half * 4);
    }
    float colmin[8];
#pragma unroll
    for (int n = 0; n < 8; n++) colmin[n] = 3.4e38f;
    float pairwise = 0.f, hxy = 0.f;
    unsigned mxs = mx >> (half * 4);
#pragma unroll
    for (int m = 0; m < 4; m++) {
      if ((mxs >> m) & 1) {
        float rowmin = 3.4e38f;
        float ax = sp[m * 3], ay = sp[m * 3 + 1], az = sp[m * 3 + 2],
              a2 = sp2[m];
#pragma unroll
        for (int n = 0; n < 8; n++) {
          if ((my >> n) & 1) {
            float s = a2 + dp2[n] -
                      2.f * (ax * dp[n * 3] + ay * dp[n * 3 + 1] +
                             az * dp[n * 3 + 2]);
            float d = sqrtf(fmaxf(s, 0.f) + 1e-12f);
            pairwise += d;
            rowmin = fminf(rowmin, d);
            colmin[n] = fminf(colmin[n], d);
          }
        }
        hxy = fmaxf(hxy, rowmin);
      }
    }
    pairwise += __shfl_xor_sync(0xffffffffu, pairwise, 1);
    hxy = fmaxf(hxy, __shfl_xor_sync(0xffffffffu, hxy, 1));
#pragma unroll
    for (int n = 0; n < 8; n++)
      colmin[n] = fminf(colmin[n], __shfl_xor_sync(0xffffffffu, colmin[n], 1));
    if (half == 0) {
      float hyx = 0.f;
#pragma unroll
      for (int n = 0; n < 8; n++)
        if ((my >> n) & 1) hyx = fmaxf(hyx, colmin[n]);
      float haus = fmaxf(hxy, hyx);
      float c0 = g_cent[is * 3 + 0] - g_cent[id * 3 + 0];
      float c1 = g_cent[is * 3 + 1] - g_cent[id * 3 + 1];
      float c2 = g_cent[is * 3 + 2] - g_cent[id * 3 + 2];
      float centroid = sqrtf(c0 * c0 + c1 * c1 + c2 * c2);
      float r0 = sRel[row * 3 + 0], r1 = sRel[row * 3 + 1],
            r2 = sRel[row * 3 + 2];
      float dist = sqrtf(r0 * r0 + r1 * r1 + r2 * r2);
      ((float4*)sInv)[row] = make_float4(dist, pairwise, centroid, haus);
    }
  }
  __syncthreads();

  int rg = tid >> 4, cg = tid & 15;
  int row0 = rg * 8;
  ull acc[8][2];

  // ---- GEMM1 (hoisted): acc = b1 + F[src] + F[dst] + inv@W1c ----
  {
    float bb0 = sb1[cg * 4 + 0], bb1 = sb1[cg * 4 + 1];
    float bb2 = sb1[cg * 4 + 2], bb3 = sb1[cg * 4 + 3];
#pragma unroll
    for (int r = 0; r < 8; r++) {
      int is = sFs[row0 + r], id = sFd[row0 + r];
      float4 fs = *(const float4*)(g_fw + (size_t)is * 128 + cg * 4);
      float4 fd = *(const float4*)(g_fw + (size_t)id * 128 + 64 + cg * 4);
      acc[r][0] = pack2f(bb0 + fs.x + fd.x, bb1 + fs.y + fd.y);
      acc[r][1] = pack2f(bb2 + fs.z + fd.z, bb3 + fs.w + fd.w);
    }
    float4 iv[8];
#pragma unroll
    for (int r = 0; r < 8; r++) iv[r] = ((const float4*)sInv)[row0 + r];
#pragma unroll
    for (int kk = 0; kk < 4; kk++) {
      ulonglong2 w = *(const ulonglong2*)(sW1c + kk * 64 + cg * 4);
#pragma unroll
      for (int r = 0; r < 8; r++) {
        ull d = dup2(((const float*)&iv[r])[kk]);
        ffma2(acc[r][0], d, w.x);
        ffma2(acc[r][1], d, w.y);
      }
    }
  }
#pragma unroll
  for (int i = 0; i < 8; i++)
#pragma unroll
    for (int p = 0; p < 2; p++) {
      float2 h = unpack2(acc[i][p]);
      h.x = silu_f(h.x);
      h.y = silu_f(h.y);
      *(float2*)(sHM + (row0 + i) * 68 + cg * 4 + 2 * p) = h;
    }
  __syncthreads();

  // ---- GEMM2: Msg = H @ W2 + b2 ----
#pragma unroll
  for (int i = 0; i < 8; i++) {
    acc[i][0] = *(const ull*)(sb2 + cg * 4 + 0);
    acc[i][1] = *(const ull*)(sb2 + cg * 4 + 2);
  }
  {
    const float* xp[8];
#pragma unroll
    for (int r = 0; r < 8; r++) xp[r] = sHM + (row0 + r) * 68;
    gemm64r<8>(xp, sW2, cg, acc);
  }
  __syncthreads();
#pragma unroll
  for (int i = 0; i < 8; i++)
#pragma unroll
    for (int p = 0; p < 2; p++) {
      float2 v = unpack2(acc[i][p]);
      *(float2*)(sHM + (row0 + i) * 68 + cg * 4 + 2 * p) = v;
    }
  __syncthreads();

  // ---- GEMM3: silu(Msg @ P1 + pb1) . P2, tanh -> wt ----
#pragma unroll
  for (int i = 0; i < 8; i++) {
    acc[i][0] = *(const ull*)(spb1 + cg * 4 + 0);
    acc[i][1] = *(const ull*)(spb1 + cg * 4 + 2);
  }
  {
    const float* xp[8];
#pragma unroll
    for (int r = 0; r < 8; r++) xp[r] = sHM + (row0 + r) * 68;
    gemm64r<8>(xp, sP1, cg, acc);
  }
  float part[8];
#pragma unroll
  for (int i = 0; i < 8; i++) {
    part[i] = 0.f;
#pragma unroll
    for (int p = 0; p < 2; p++) {
      float2 h = unpack2(acc[i][p]);
      part[i] = fmaf(silu_f(h.x), sP2[cg * 4 + 2 * p], part[i]);
      part[i] = fmaf(silu_f(h.y), sP2[cg * 4 + 2 * p + 1], part[i]);
    }
  }
#pragma unroll
  for (int i = 0; i < 8; i++) {
    float v = part[i];
    v += __shfl_xor_sync(0xffffffffu, v, 1);
    v += __shfl_xor_sync(0xffffffffu, v, 2);
    v += __shfl_xor_sync(0xffffffffu, v, 4);
    v += __shfl_xor_sync(0xffffffffu, v, 8);
    if (cg == 0) sWt[row0 + i] = tanhf(v + pb2v);
  }
  __syncthreads();

  // ---- scatter ----
  int lr = tid >> 1, ts = tid & 1;
  int ob = sDst[lr];
  float* ap = g_agg + (size_t)ob * kH + ts * 32;
  const float* mp = sHM + lr * 68 + ts * 32;
#pragma unroll
  for (int q = 0; q < 8; q++)
    red_add_v4(ap + q * 4, mp[q * 4 + 0], mp[q * 4 + 1], mp[q * 4 + 2],
               mp[q * 4 + 3]);
  if (ts == 0) {
    float w = sWt[lr];
    float* pp = g_posupd + (size_t)ob * kP;
    atomicAdd(pp + 0, w * sRel[lr * 3 + 0]);
    atomicAdd(pp + 1, w * sRel[lr * 3 + 1]);
    atomicAdd(pp + 2, w * sRel[lr * 3 + 2]);
  }
}

__global__ void __launch_bounds__(TB, 2) node_kernel(
    const float* __restrict__ features, const float* __restrict__ degree,
    const float* __restrict__ U1, const float* __restrict__ ub1,
    const float* __restrict__ U2, const float* __restrict__ ub2,
    float* __restrict__ out_feat) {
  extern __shared__ float smf[];
  float* sU1 = smf + NOFF_U1;
  float* sU2 = smf + NOFF_U2;
  float* sub1 = smf + NOFF_UB1;
  float* sub2 = smf + NOFF_UB2;
  float* sHM = smf + NOFF_HM;  // [160][68]
  float* sInvD = smf + NOFF_IDG;

  int tid = threadIdx.x;
  for (int i = tid; i < 128 * 64; i += TB) sU1[i] = U1[i];
  for (int i = tid; i < 64 * 64; i += TB) sU2[i] = U2[i];
  if (tid < 64) { sub1[tid] = ub1[tid]; sub2[tid] = ub2[tid]; }

  if (tid < NTILE) {
    int gr = blockIdx.x * NTILE + tid;
    int c = gr % kC;
    sInvD[tid] = 1.f / fmaxf(degree[c], 1.f);
  }
  __syncthreads();

  int rg = tid >> 4, cg = tid & 15;
  int row0 = rg * 5;
  int gr0 = blockIdx.x * NTILE + row0;

  ull acc[5][2];
#pragma unroll
  for (int i = 0; i < 5; i++) { acc[i][0] = 0ull; acc[i][1] = 0ull; }

  {
    const float* xp[5];
#pragma unroll
    for (int r = 0; r < 5; r++) xp[r] = g_agg + (size_t)(gr0 + r) * kH;
    gemm64r<5>(xp, sU1 + 64 * 64, cg, acc);
  }
  {
    ull bias0 = *(const ull*)(sub1 + cg * 4 + 0);
    ull bias1 = *(const ull*)(sub1 + cg * 4 + 2);
#pragma unroll
    for (int i = 0; i < 5; i++) {
      ull dv = dup2(sInvD[row0 + i]);
      fma2_scale_bias(acc[i][0], dv, bias0);
      fma2_scale_bias(acc[i][1], dv, bias1);
    }
  }
  {
    const float* xp[5];
#pragma unroll
    for (int r = 0; r < 5; r++) xp[r] = features + (size_t)(gr0 + r) * kH;
    gemm64r<5>(xp, sU1, cg, acc);
  }
#pragma unroll
  for (int i = 0; i < 5; i++)
#pragma unroll
    for (int p = 0; p < 2; p++) {
      float2 h = unpack2(acc[i][p]);
      h.x = silu_f(h.x);
      h.y = silu_f(h.y);
      *(float2*)(sHM + (row0 + i) * 68 + cg * 4 + 2 * p) = h;
    }
  __syncthreads();

#pragma unroll
  for (int i = 0; i < 5; i++) {
    acc[i][0] = *(const ull*)(sub2 + cg * 4 + 0);
    acc[i][1] = *(const ull*)(sub2 + cg * 4 + 2);
  }
  {
    const float* xp[5];
#pragma unroll
    for (int r = 0; r < 5; r++) xp[r] = sHM + (row0 + r) * 68;
    gemm64r<5>(xp, sU2, cg, acc);
  }
#pragma unroll
  for (int i = 0; i < 5; i++) {
    int g2 = gr0 + i;
    const float4 f = ((const float4*)(features + (size_t)g2 * kH))[cg];
    float2 v0 = unpack2(acc[i][0]);
    float2 v1 = unpack2(acc[i][1]);
    float4 o;
    o.x = f.x + v0.x;
    o.y = f.y + v0.y;
    o.z = f.z + v1.x;
    o.w = f.w + v1.y;
    ((float4*)(out_feat + (size_t)g2 * kH))[cg] = o;
  }
}

__global__ void pos_kernel(const float* __restrict__ positions,
                           float* __restrict__ out_pos) {
  int i = blockIdx.x * blockDim.x + threadIdx.x;
  if (i < kNC * kP) out_pos[i] = positions[i] + g_posupd[i];
}

extern "C" void kernel_launch(void* const* d_in, const int* in_sizes, int n_in,
                              void* d_out, int out_size) {
  const float* features = (const float*)d_in[0];
  const float* positions = (const float*)d_in[1];
  const int* edge_index = (const int*)d_in[2];
  const float* degree = (const float*)d_in[3];
  const int* cni = (const int*)d_in[4];
  const float* mask = (const float*)d_in[5];
  const float* W1 = (const float*)d_in[6];
  const float* b1 = (const float*)d_in[7];
  const float* W2 = (const float*)d_in[8];
  const float* b2 = (const float*)d_in[9];
  const float* P1 = (const float*)d_in[10];
  const float* pb1 = (const float*)d_in[11];
  const float* P2 = (const float*)d_in[12];
  const float* pb2 = (const float*)d_in[13];
  const float* U1 = (const float*)d_in[14];
  const float* ub1 = (const float*)d_in[15];
  const float* U2 = (const float*)d_in[16];
  const float* ub2 = (const float*)d_in[17];

  float* out_feat = (float*)d_out;
  float* out_pos = out_feat + (size_t)kNC * kH;

  size_t msg_smem = (size_t)MSG_SMEM_FLOATS * sizeof(float);    // 75,264 B
  size_t node_smem = (size_t)NODE_SMEM_FLOATS * sizeof(float);  // 93,824 B
  cudaFuncSetAttribute(msg_kernel, cudaFuncAttributeMaxDynamicSharedMemorySize,
                       (int)msg_smem);
  cudaFuncSetAttribute(node_kernel, cudaFuncAttributeMaxDynamicSharedMemorySize,
                       (int)node_smem);

  zero_kernel<<<(kNC * kH + 255) / 256, 256>>>();
  prep_kernel<<<(kNC + 255) / 256, 256>>>(positions, cni, mask);
  featw_kernel<<<kNC / 40, 256>>>(features, W1);
  msg_kernel<<<kNR / TILE, TBM, msg_smem>>>(features, positions, edge_index, W1,
                                            b1, W2, b2, P1, pb1, P2, pb2);
  node_kernel<<<kNC / NTILE, TB, node_smem>>>(features, degree, U1, ub1, U2,
                                              ub2, out_feat);
  pos_kernel<<<(kNC * kP + 255) / 256, 256>>>(positions, out_pos);
}

// round 13
// speedup vs baseline: 3.7292x; 1.0001x over previous
#include <cuda_runtime.h>
#include <math.h>

typedef unsigned long long ull;

namespace {
constexpr int kB = 2, kC = 20000, kH = 64, kM = 8, kE = 200000, kP = 3;
constexpr int kNR = kB * kE;  // 400000 = 3125 * 128
constexpr int kNC = kB * kC;  // 40000
constexpr int TILE = 128;
constexpr int TBM = 256;   // msg threads
constexpr int NTILE = 160; // node rows/block (250 blocks exact)
constexpr int TB = 512;    // node threads

// msg_kernel shared layout (float offsets)  [identical to R9/R12]
constexpr int OFF_W1C = 0;      // 4*64 = 256
constexpr int OFF_W2 = 256;     // 4096
constexpr int OFF_P1 = 4352;    // 4096
constexpr int OFF_P2 = 8448;    // 64
constexpr int OFF_B1 = 8512;    // 64
constexpr int OFF_B2 = 8576;    // 64
constexpr int OFF_PB1 = 8640;   // 64
constexpr int OFF_HM = 8704;    // 128*68 = 8704 (H then Msg)
constexpr int OFF_INV = 17408;  // 128*4
constexpr int OFF_REL = 17920;  // 384
constexpr int OFF_WT = 18304;   // 128
constexpr int OFF_DST = 18432;  // 128
constexpr int OFF_FS = 18560;   // 128
constexpr int OFF_FD = 18688;   // 128
constexpr int MSG_SMEM_FLOATS = 18816;  // 75,264 B -> 3 blocks/SM

// node_kernel shared layout
constexpr int NOFF_U1 = 0;       // 8192
constexpr int NOFF_U2 = 8192;    // 4096
constexpr int NOFF_UB1 = 12288;  // 64
constexpr int NOFF_UB2 = 12352;  // 64
constexpr int NOFF_HM = 12416;   // 160*68 = 10880
constexpr int NOFF_IDG = 23296;  // 160
constexpr int NODE_SMEM_FLOATS = 23456;  // 93,824 B -> 2 blocks/SM
}  // namespace

// Scratch (static device globals)
__device__ float g_agg[kNC * kH];
__device__ float g_posupd[kNC * kP];
__device__ float g_npos[kNC * kM * 3];
__device__ float g_np2[kNC * kM];
__device__ float g_cent[kNC * 3];
__device__ unsigned g_mbits[kC];
__device__ float g_fw[(size_t)kNC * 128];  // [node][0:64]=f@W1a, [64:128]=f@W1b

// ---- packed f32x2 helpers ----
__device__ __forceinline__ ull dup2(float v) {
  ull r;
  asm("mov.b64 %0, {%1, %1};" : "=l"(r) : "f"(v));
  return r;
}
__device__ __forceinline__ ull pack2f(float a, float b) {
  ull r;
  asm("mov.b64 %0, {%1, %2};" : "=l"(r) : "f"(a), "f"(b));
  return r;
}
__device__ __forceinline__ void ffma2(ull& d, ull a, ull b) {
  asm("fma.rn.f32x2 %0, %1, %2, %0;" : "+l"(d) : "l"(a), "l"(b));
}
__device__ __forceinline__ void fma2_scale_bias(ull& d, ull a, ull b) {
  asm("fma.rn.f32x2 %0, %0, %1, %2;" : "+l"(d) : "l"(a), "l"(b));
}
__device__ __forceinline__ float2 unpack2(ull v) {
  float2 f;
  asm("mov.b64 {%0, %1}, %2;" : "=f"(f.x), "=f"(f.y) : "l"(v));
  return f;
}
__device__ __forceinline__ void red_add_v4(float* p, float a, float b, float c,
                                           float d) {
  asm volatile("red.global.add.v4.f32 [%0], {%1, %2, %3, %4};" ::"l"(p), "f"(a),
               "f"(b), "f"(c), "f"(d)
               : "memory");
}
// silu via single-MUFU tanh.approx
__device__ __forceinline__ float silu_f(float v) {
  float t;
  asm("tanh.approx.f32 %0, %1;" : "=f"(t) : "f"(0.5f * v));
  return 0.5f * v * (1.f + t);
}

// R-row x 4-col tile, 64 k-steps, W row-major [64][64] in smem
template <int R>
__device__ __forceinline__ void gemm64r(const float* const xp[R],
                                        const float* __restrict__ W, int cg,
                                        ull (*acc)[2]) {
#pragma unroll
  for (int g = 0; g < 16; g++) {
    float4 xv[R];
#pragma unroll
    for (int r = 0; r < R; r++) xv[r] = *(const float4*)(xp[r] + 4 * g);
#pragma unroll
    for (int kk = 0; kk < 4; kk++) {
      ulonglong2 w = *(const ulonglong2*)(W + (4 * g + kk) * 64 + cg * 4);
#pragma unroll
      for (int r = 0; r < R; r++) {
        ull d = dup2(((const float*)&xv[r])[kk]);
        ffma2(acc[r][0], d, w.x);
        ffma2(acc[r][1], d, w.y);
      }
    }
  }
}

// merged zero + prep (one launch)
__global__ void prep_kernel(const float* __restrict__ positions,
                            const int* __restrict__ cni,
                            const float* __restrict__ mask) {
  int i = blockIdx.x * blockDim.x + threadIdx.x;
  if (i < kNC * kH) g_agg[i] = 0.f;
  if (i < kNC * kP) g_posupd[i] = 0.f;
  if (i >= kNC) return;
  int b = i / kC, c = i - b * kC;
  float sx = 0.f, sy = 0.f, sz = 0.f, cnt = 0.f;
  unsigned bits = 0;
#pragma unroll
  for (int m = 0; m < kM; m++) {
    int idx = cni[c * kM + m];
    const float* p = positions + ((size_t)b * kC + idx) * kP;
    float x = p[0], y = p[1], z = p[2];
    g_npos[((size_t)i * kM + m) * 3 + 0] = x;
    g_npos[((size_t)i * kM + m) * 3 + 1] = y;
    g_npos[((size_t)i * kM + m) * 3 + 2] = z;
    g_np2[i * kM + m] = x * x + y * y + z * z;
    float mk = mask[c * kM + m];
    if (mk > 0.f) { bits |= (1u << m); sx += x; sy += y; sz += z; cnt += 1.f; }
  }
  float den = fmaxf(cnt, 1e-12f);
  g_cent[i * 3 + 0] = sx / den;
  g_cent[i * 3 + 1] = sy / den;
  g_cent[i * 3 + 2] = sz / den;
  if (b == 0) g_mbits[c] = bits;
}

// F[node] = [features@W1a | features@W1b]  (hoisted GEMM1 node terms)
// 4 rows/thread, 256 threads -> ~60 regs -> 4 blocks/SM target
__global__ void __launch_bounds__(256) featw_kernel(
    const float* __restrict__ features, const float* __restrict__ W1) {
  __shared__ float sW[64 * 128];
  int tid = threadIdx.x;
  for (int i = tid; i < 64 * 128; i += 256) {
    int k = i >> 7, n = i & 127;
    sW[i] = (n < 64) ? W1[k * 64 + n] : W1[(64 + k) * 64 + (n - 64)];
  }
  __syncthreads();
  int rg = tid >> 5, cg = tid & 31;
  int row0 = blockIdx.x * 32 + rg * 4;
  ull acc[4][2];
#pragma unroll
  for (int r = 0; r < 4; r++) { acc[r][0] = 0ull; acc[r][1] = 0ull; }
  const float* xp[4];
#pragma unroll
  for (int r = 0; r < 4; r++) xp[r] = features + (size_t)(row0 + r) * kH;
#pragma unroll
  for (int g = 0; g < 16; g++) {
    float4 xv[4];
#pragma unroll
    for (int r = 0; r < 4; r++) xv[r] = *(const float4*)(xp[r] + 4 * g);
#pragma unroll
    for (int kk = 0; kk < 4; kk++) {
      ulonglong2 w = *(const ulonglong2*)(sW + (4 * g + kk) * 128 + cg * 4);
#pragma unroll
      for (int r = 0; r < 4; r++) {
        ull d = dup2(((const float*)&xv[r])[kk]);
        ffma2(acc[r][0], d, w.x);
        ffma2(acc[r][1], d, w.y);
      }
    }
  }
#pragma unroll
  for (int r = 0; r < 4; r++) {
    float2 v0 = unpack2(acc[r][0]);
    float2 v1 = unpack2(acc[r][1]);
    *(float4*)(g_fw + (size_t)(row0 + r) * 128 + cg * 4) =
        make_float4(v0.x, v0.y, v1.x, v1.y);
  }
}

// msg_kernel: exact R9/R12 structure (233us, spill-free at occupancy 3)
__global__ void __launch_bounds__(TBM, 3) msg_kernel(
    const float* __restrict__ features, const float* __restrict__ positions,
    const int* __restrict__ ei,
    const float* __restrict__ W1, const float* __restrict__ b1,
    const float* __restrict__ W2, const float* __restrict__ b2,
    const float* __restrict__ P1, const float* __restrict__ pb1,
    const float* __restrict__ P2, const float* __restrict__ pb2) {
  extern __shared__ float sm[];
  float* sW1c = sm + OFF_W1C;
  float* sW2 = sm + OFF_W2;
  float* sP1 = sm + OFF_P1;
  float* sP2 = sm + OFF_P2;
  float* sb1 = sm + OFF_B1;
  float* sb2 = sm + OFF_B2;
  float* spb1 = sm + OFF_PB1;
  float* sHM = sm + OFF_HM;    // [128][68] H, then Msg
  float* sInv = sm + OFF_INV;  // [128][4]
  float* sRel = sm + OFF_REL;
  float* sWt = sm + OFF_WT;
  int* sDst = (int*)(sm + OFF_DST);
  int* sFs = (int*)(sm + OFF_FS);
  int* sFd = (int*)(sm + OFF_FD);

  int tid = threadIdx.x;
  for (int i = tid; i < 256; i += TBM) sW1c[i] = W1[128 * 64 + i];
  for (int i = tid; i < 64 * 64; i += TBM) { sW2[i] = W2[i]; sP1[i] = P1[i]; }
  if (tid < 64) { sP2[tid] = P2[tid]; sb1[tid] = b1[tid]; sb2[tid] = b2[tid]; spb1[tid] = pb1[tid]; }
  float pb2v = pb2[0];

  // ---- gather (node indices + rel) ----
  if (tid < TILE) {
    int gr = blockIdx.x * TILE + tid;
    int b = gr / kE, e = gr - b * kE;
    int src = ei[e], dst = ei[kE + e];
    int is = b * kC + src, id = b * kC + dst;
    sFs[tid] = is;
    sFd[tid] = id;
    sDst[tid] = id;
    const float* ps = positions + (size_t)is * kP;
    const float* pd = positions + (size_t)id * kP;
    sRel[tid * 3 + 0] = ps[0] - pd[0];
    sRel[tid * 3 + 1] = ps[1] - pd[1];
    sRel[tid * 3 + 2] = ps[2] - pd[2];
  }
  __syncthreads();

  // ---- fused invariants: 2 threads per row ----
  {
    int row = tid >> 1, half = tid & 1;
    int is = sFs[row], id = sFd[row];
    unsigned mx = g_mbits[is >= kC ? is - kC : is];
    unsigned my = g_mbits[id >= kC ? id - kC : id];
    float dp[24], dp2[8];
    {
      const float4* a = (const float4*)(g_npos + (size_t)id * 24);
#pragma unroll
      for (int q = 0; q < 6; q++) ((float4*)dp)[q] = a[q];
      const float4* d2 = (const float4*)(g_np2 + (size_t)id * 8);
      ((float4*)dp2)[0] = d2[0];
      ((float4*)dp2)[1] = d2[1];
    }
    float sp[12], sp2[4];
    {
      const float4* a = (const float4*)(g_npos + (size_t)is * 24 + half * 12);
#pragma unroll
      for (int q = 0; q < 3; q++) ((float4*)sp)[q] = a[q];
      ((float4*)sp2)[0] = *(const float4*)(g_np2 + (size_t)is * 8 + half * 4);
    }
    float colmin[8];
#pragma unroll
    for (int n = 0; n < 8; n++) colmin[n] = 3.4e38f;
    float pairwise = 0.f, hxy = 0.f;
    unsigned mxs = mx >> (half * 4);
#pragma unroll
    for (int m = 0; m < 4; m++) {
      if ((mxs >> m) & 1) {
        float rowmin = 3.4e38f;
        float ax = sp[m * 3], ay = sp[m * 3 + 1], az = sp[m * 3 + 2],
              a2 = sp2[m];
#pragma unroll
        for (int n = 0; n < 8; n++) {
          if ((my >> n) & 1) {
            float s = a2 + dp2[n] -
                      2.f * (ax * dp[n * 3] + ay * dp[n * 3 + 1] +
                             az * dp[n * 3 + 2]);
            float d = sqrtf(fmaxf(s, 0.f) + 1e-12f);
            pairwise += d;
            rowmin = fminf(rowmin, d);
            colmin[n] = fminf(colmin[n], d);
          }
        }
        hxy = fmaxf(hxy, rowmin);
      }
    }
    pairwise += __shfl_xor_sync(0xffffffffu, pairwise, 1);
    hxy = fmaxf(hxy, __shfl_xor_sync(0xffffffffu, hxy, 1));
#pragma unroll
    for (int n = 0; n < 8; n++)
      colmin[n] = fminf(colmin[n], __shfl_xor_sync(0xffffffffu, colmin[n], 1));
    if (half == 0) {
      float hyx = 0.f;
#pragma unroll
      for (int n = 0; n < 8; n++)
        if ((my >> n) & 1) hyx = fmaxf(hyx, colmin[n]);
      float haus = fmaxf(hxy, hyx);
      float c0 = g_cent[is * 3 + 0] - g_cent[id * 3 + 0];
      float c1 = g_cent[is * 3 + 1] - g_cent[id * 3 + 1];
      float c2 = g_cent[is * 3 + 2] - g_cent[id * 3 + 2];
      float centroid = sqrtf(c0 * c0 + c1 * c1 + c2 * c2);
      float r0 = sRel[row * 3 + 0], r1 = sRel[row * 3 + 1],
            r2 = sRel[row * 3 + 2];
      float dist = sqrtf(r0 * r0 + r1 * r1 + r2 * r2);
      ((float4*)sInv)[row] = make_float4(dist, pairwise, centroid, haus);
    }
  }
  __syncthreads();

  int rg = tid >> 4, cg = tid & 15;
  int row0 = rg * 8;
  ull acc[8][2];

  // ---- GEMM1 (hoisted): acc = b1 + F[src] + F[dst] + inv@W1c ----
  {
    float bb0 = sb1[cg * 4 + 0], bb1 = sb1[cg * 4 + 1];
    float bb2 = sb1[cg * 4 + 2], bb3 = sb1[cg * 4 + 3];
#pragma unroll
    for (int r = 0; r < 8; r++) {
      int is = sFs[row0 + r], id = sFd[row0 + r];
      float4 fs = *(const float4*)(g_fw + (size_t)is * 128 + cg * 4);
      float4 fd = *(const float4*)(g_fw + (size_t)id * 128 + 64 + cg * 4);
      acc[r][0] = pack2f(bb0 + fs.x + fd.x, bb1 + fs.y + fd.y);
      acc[r][1] = pack2f(bb2 + fs.z + fd.z, bb3 + fs.w + fd.w);
    }
    float4 iv[8];
#pragma unroll
    for (int r = 0; r < 8; r++) iv[r] = ((const float4*)sInv)[row0 + r];
#pragma unroll
    for (int kk = 0; kk < 4; kk++) {
      ulonglong2 w = *(const ulonglong2*)(sW1c + kk * 64 + cg * 4);
#pragma unroll
      for (int r = 0; r < 8; r++) {
        ull d = dup2(((const float*)&iv[r])[kk]);
        ffma2(acc[r][0], d, w.x);
        ffma2(acc[r][1], d, w.y);
      }
    }
  }
#pragma unroll
  for (int i = 0; i < 8; i++)
#pragma unroll
    for (int p = 0; p < 2; p++) {
      float2 h = unpack2(acc[i][p]);
      h.x = silu_f(h.x);
      h.y = silu_f(h.y);
      *(float2*)(sHM + (row0 + i) * 68 + cg * 4 + 2 * p) = h;
    }
  __syncthreads();

  // ---- GEMM2: Msg = H @ W2 + b2 ----
#pragma unroll
  for (int i = 0; i < 8; i++) {
    acc[i][0] = *(const ull*)(sb2 + cg * 4 + 0);
    acc[i][1] = *(const ull*)(sb2 + cg * 4 + 2);
  }
  {
    const float* xp[8];
#pragma unroll
    for (int r = 0; r < 8; r++) xp[r] = sHM + (row0 + r) * 68;
    gemm64r<8>(xp, sW2, cg, acc);
  }
  __syncthreads();
#pragma unroll
  for (int i = 0; i < 8; i++)
#pragma unroll
    for (int p = 0; p < 2; p++) {
      float2 v = unpack2(acc[i][p]);
      *(float2*)(sHM + (row0 + i) * 68 + cg * 4 + 2 * p) = v;
    }
  __syncthreads();

  // ---- GEMM3: silu(Msg @ P1 + pb1) . P2, tanh -> wt ----
#pragma unroll
  for (int i = 0; i < 8; i++) {
    acc[i][0] = *(const ull*)(spb1 + cg * 4 + 0);
    acc[i][1] = *(const ull*)(spb1 + cg * 4 + 2);
  }
  {
    const float* xp[8];
#pragma unroll
    for (int r = 0; r < 8; r++) xp[r] = sHM + (row0 + r) * 68;
    gemm64r<8>(xp, sP1, cg, acc);
  }
  float part[8];
#pragma unroll
  for (int i = 0; i < 8; i++) {
    part[i] = 0.f;
#pragma unroll
    for (int p = 0; p < 2; p++) {
      float2 h = unpack2(acc[i][p]);
      part[i] = fmaf(silu_f(h.x), sP2[cg * 4 + 2 * p], part[i]);
      part[i] = fmaf(silu_f(h.y), sP2[cg * 4 + 2 * p + 1], part[i]);
    }
  }
#pragma unroll
  for (int i = 0; i < 8; i++) {
    float v = part[i];
    v += __shfl_xor_sync(0xffffffffu, v, 1);
    v += __shfl_xor_sync(0xffffffffu, v, 2);
    v += __shfl_xor_sync(0xffffffffu, v, 4);
    v += __shfl_xor_sync(0xffffffffu, v, 8);
    if (cg == 0) sWt[row0 + i] = tanhf(v + pb2v);
  }
  __syncthreads();

  // ---- scatter ----
  int lr = tid >> 1, ts = tid & 1;
  int ob = sDst[lr];
  float* ap = g_agg + (size_t)ob * kH + ts * 32;
  const float* mp = sHM + lr * 68 + ts * 32;
#pragma unroll
  for (int q = 0; q < 8; q++)
    red_add_v4(ap + q * 4, mp[q * 4 + 0], mp[q * 4 + 1], mp[q * 4 + 2],
               mp[q * 4 + 3]);
  if (ts == 0) {
    float w = sWt[lr];
    float* pp = g_posupd + (size_t)ob * kP;
    atomicAdd(pp + 0, w * sRel[lr * 3 + 0]);
    atomicAdd(pp + 1, w * sRel[lr * 3 + 1]);
    atomicAdd(pp + 2, w * sRel[lr * 3 + 2]);
  }
}

__global__ void __launch_bounds__(TB, 2) node_kernel(
    const float* __restrict__ features, const float* __restrict__ positions,
    const float* __restrict__ degree,
    const float* __restrict__ U1, const float* __restrict__ ub1,
    const float* __restrict__ U2, const float* __restrict__ ub2,
    float* __restrict__ out_feat, float* __restrict__ out_pos) {
  extern __shared__ float smf[];
  float* sU1 = smf + NOFF_U1;
  float* sU2 = smf + NOFF_U2;
  float* sub1 = smf + NOFF_UB1;
  float* sub2 = smf + NOFF_UB2;
  float* sHM = smf + NOFF_HM;  // [160][68]
  float* sInvD = smf + NOFF_IDG;

  int tid = threadIdx.x;
  for (int i = tid; i < 128 * 64; i += TB) sU1[i] = U1[i];
  for (int i = tid; i < 64 * 64; i += TB) sU2[i] = U2[i];
  if (tid < 64) { sub1[tid] = ub1[tid]; sub2[tid] = ub2[tid]; }

  if (tid < NTILE) {
    int gr = blockIdx.x * NTILE + tid;
    int c = gr % kC;
    sInvD[tid] = 1.f / fmaxf(degree[c], 1.f);
  }
  // fused pos update: block b owns pos elements [480b, 480b+480)
  if (tid < 480) {
    int pi = blockIdx.x * 480 + tid;
    out_pos[pi] = positions[pi] + g_posupd[pi];
  }
  __syncthreads();

  int rg = tid >> 4, cg = tid & 15;
  int row0 = rg * 5;
  int gr0 = blockIdx.x * NTILE + row0;

  ull acc[5][2];
#pragma unroll
  for (int i = 0; i < 5; i++) { acc[i][0] = 0ull; acc[i][1] = 0ull; }

  {
    const float* xp[5];
#pragma unroll
    for (int r = 0; r < 5; r++) xp[r] = g_agg + (size_t)(gr0 + r) * kH;
    gemm64r<5>(xp, sU1 + 64 * 64, cg, acc);
  }
  {
    ull bias0 = *(const ull*)(sub1 + cg * 4 + 0);
    ull bias1 = *(const ull*)(sub1 + cg * 4 + 2);
#pragma unroll
    for (int i = 0; i < 5; i++) {
      ull dv = dup2(sInvD[row0 + i]);
      fma2_scale_bias(acc[i][0], dv, bias0);
      fma2_scale_bias(acc[i][1], dv, bias1);
    }
  }
  {
    const float* xp[5];
#pragma unroll
    for (int r = 0; r < 5; r++) xp[r] = features + (size_t)(gr0 + r) * kH;
    gemm64r<5>(xp, sU1, cg, acc);
  }
#pragma unroll
  for (int i = 0; i < 5; i++)
#pragma unroll
    for (int p = 0; p < 2; p++) {
      float2 h = unpack2(acc[i][p]);
      h.x = silu_f(h.x);
      h.y = silu_f(h.y);
      *(float2*)(sHM + (row0 + i) * 68 + cg * 4 + 2 * p) = h;
    }
  __syncthreads();

#pragma unroll
  for (int i = 0; i < 5; i++) {
    acc[i][0] = *(const ull*)(sub2 + cg * 4 + 0);
    acc[i][1] = *(const ull*)(sub2 + cg * 4 + 2);
  }
  {
    const float* xp[5];
#pragma unroll
    for (int r = 0; r < 5; r++) xp[r] = sHM + (row0 + r) * 68;
    gemm64r<5>(xp, sU2, cg, acc);
  }
#pragma unroll
  for (int i = 0; i < 5; i++) {
    int g2 = gr0 + i;
    const float4 f = ((const float4*)(features + (size_t)g2 * kH))[cg];
    float2 v0 = unpack2(acc[i][0]);
    float2 v1 = unpack2(acc[i][1]);
    float4 o;
    o.x = f.x + v0.x;
    o.y = f.y + v0.y;
    o.z = f.z + v1.x;
    o.w = f.w + v1.y;
    ((float4*)(out_feat + (size_t)g2 * kH))[cg] = o;
  }
}

extern "C" void kernel_launch(void* const* d_in, const int* in_sizes, int n_in,
                              void* d_out, int out_size) {
  const float* features = (const float*)d_in[0];
  const float* positions = (const float*)d_in[1];
  const int* edge_index = (const int*)d_in[2];
  const float* degree = (const float*)d_in[3];
  const int* cni = (const int*)d_in[4];
  const float* mask = (const float*)d_in[5];
  const float* W1 = (const float*)d_in[6];
  const float* b1 = (const float*)d_in[7];
  const float* W2 = (const float*)d_in[8];
  const float* b2 = (const float*)d_in[9];
  const float* P1 = (const float*)d_in[10];
  const float* pb1 = (const float*)d_in[11];
  const float* P2 = (const float*)d_in[12];
  const float* pb2 = (const float*)d_in[13];
  const float* U1 = (const float*)d_in[14];
  const float* ub1 = (const float*)d_in[15];
  const float* U2 = (const float*)d_in[16];
  const float* ub2 = (const float*)d_in[17];

  float* out_feat = (float*)d_out;
  float* out_pos = out_feat + (size_t)kNC * kH;

  size_t msg_smem = (size_t)MSG_SMEM_FLOATS * sizeof(float);    // 75,264 B
  size_t node_smem = (size_t)NODE_SMEM_FLOATS * sizeof(float);  // 93,824 B
  cudaFuncSetAttribute(msg_kernel, cudaFuncAttributeMaxDynamicSharedMemorySize,
                       (int)msg_smem);
  cudaFuncSetAttribute(node_kernel, cudaFuncAttributeMaxDynamicSharedMemorySize,
                       (int)node_smem);

  prep_kernel<<<(kNC * kH + 255) / 256, 256>>>(positions, cni, mask);
  featw_kernel<<<kNC / 32, 256>>>(features, W1);
  msg_kernel<<<kNR / TILE, TBM, msg_smem>>>(features, positions, edge_index, W1,
                                            b1, W2, b2, P1, pb1, P2, pb2);
  node_kernel<<<kNC / NTILE, TB, node_smem>>>(features, positions, degree, U1,
                                              ub1, U2, ub2, out_feat, out_pos);
}

// round 14
// speedup vs baseline: 3.7713x; 1.0113x over previous
#include <cuda_runtime.h>
#include <math.h>

typedef unsigned long long ull;

namespace {
constexpr int kB = 2, kC = 20000, kH = 64, kM = 8, kE = 200000, kP = 3;
constexpr int kNR = kB * kE;  // 400000 = 3125 * 128
constexpr int kNC = kB * kC;  // 40000
constexpr int TILE = 128;
constexpr int TBM = 256;   // msg threads
constexpr int NTILE = 160; // node rows/block (250 blocks exact)
constexpr int TB = 512;    // node threads

// msg_kernel shared layout (float offsets)
constexpr int OFF_W1C = 0;      // 4*64 = 256
constexpr int OFF_W2 = 256;     // 4096
constexpr int OFF_P1 = 4352;    // 4096
constexpr int OFF_P2 = 8448;    // 64
constexpr int OFF_B1 = 8512;    // 64 (unused now; layout kept)
constexpr int OFF_B2 = 8576;    // 64
constexpr int OFF_PB1 = 8640;   // 64
constexpr int OFF_HM = 8704;    // 128*68 = 8704 (H then Msg)
constexpr int OFF_INV = 17408;  // 128*4
constexpr int OFF_REL = 17920;  // 384
constexpr int OFF_WT = 18304;   // 128
constexpr int OFF_DST = 18432;  // 128
constexpr int OFF_FS = 18560;   // 128
constexpr int OFF_FD = 18688;   // 128
constexpr int MSG_SMEM_FLOATS = 18816;  // 75,264 B -> 3 blocks/SM

// node_kernel shared layout
constexpr int NOFF_U1 = 0;       // 8192
constexpr int NOFF_U2 = 8192;    // 4096
constexpr int NOFF_UB1 = 12288;  // 64
constexpr int NOFF_UB2 = 12352;  // 64
constexpr int NOFF_HM = 12416;   // 160*68 = 10880
constexpr int NOFF_IDG = 23296;  // 160
constexpr int NODE_SMEM_FLOATS = 23456;  // 93,824 B -> 2 blocks/SM
}  // namespace

// Scratch (static device globals)
__device__ float g_agg[kNC * kH];
__device__ float g_posupd[kNC * kP];
__device__ float g_npos[kNC * kM * 3];
__device__ float g_np2[kNC * kM];
__device__ float g_cent[kNC * 3];
__device__ unsigned g_mbits[kC];
__device__ float g_fw[(size_t)kNC * 128];  // [node][0:64]=f@W1a + b1, [64:128]=f@W1b

// ---- packed f32x2 helpers ----
__device__ __forceinline__ ull dup2(float v) {
  ull r;
  asm("mov.b64 %0, {%1, %1};" : "=l"(r) : "f"(v));
  return r;
}
__device__ __forceinline__ ull pack2f(float a, float b) {
  ull r;
  asm("mov.b64 %0, {%1, %2};" : "=l"(r) : "f"(a), "f"(b));
  return r;
}
__device__ __forceinline__ void ffma2(ull& d, ull a, ull b) {
  asm("fma.rn.f32x2 %0, %1, %2, %0;" : "+l"(d) : "l"(a), "l"(b));
}
__device__ __forceinline__ void fma2_scale_bias(ull& d, ull a, ull b) {
  asm("fma.rn.f32x2 %0, %0, %1, %2;" : "+l"(d) : "l"(a), "l"(b));
}
__device__ __forceinline__ float2 unpack2(ull v) {
  float2 f;
  asm("mov.b64 {%0, %1}, %2;" : "=f"(f.x), "=f"(f.y) : "l"(v));
  return f;
}
__device__ __forceinline__ void red_add_v4(float* p, float a, float b, float c,
                                           float d) {
  asm volatile("red.global.add.v4.f32 [%0], {%1, %2, %3, %4};" ::"l"(p), "f"(a),
               "f"(b), "f"(c), "f"(d)
               : "memory");
}
// silu via single-MUFU tanh.approx
__device__ __forceinline__ float silu_f(float v) {
  float t;
  asm("tanh.approx.f32 %0, %1;" : "=f"(t) : "f"(0.5f * v));
  return 0.5f * v * (1.f + t);
}

// R-row x 4-col tile, 64 k-steps, W row-major [64][64] in smem
template <int R>
__device__ __forceinline__ void gemm64r(const float* const xp[R],
                                        const float* __restrict__ W, int cg,
                                        ull (*acc)[2]) {
#pragma unroll
  for (int g = 0; g < 16; g++) {
    float4 xv[R];
#pragma unroll
    for (int r = 0; r < R; r++) xv[r] = *(const float4*)(xp[r] + 4 * g);
#pragma unroll
    for (int kk = 0; kk < 4; kk++) {
      ulonglong2 w = *(const ulonglong2*)(W + (4 * g + kk) * 64 + cg * 4);
#pragma unroll
      for (int r = 0; r < R; r++) {
        ull d = dup2(((const float*)&xv[r])[kk]);
        ffma2(acc[r][0], d, w.x);
        ffma2(acc[r][1], d, w.y);
      }
    }
  }
}

// ===== merged prep + zero + featw: 1250 blocks x 256 threads, 32 nodes each
__global__ void __launch_bounds__(256) prepfw_kernel(
    const float* __restrict__ features, const float* __restrict__ W1,
    const float* __restrict__ b1, const float* __restrict__ positions,
    const int* __restrict__ cni, const float* __restrict__ mask) {
  __shared__ float sW[64 * 128];
  int tid = threadIdx.x;
  int nb = blockIdx.x * 32;  // first node of this block

  for (int i = tid; i < 64 * 128; i += 256) {
    int k = i >> 7, n = i & 127;
    sW[i] = (n < 64) ? W1[k * 64 + n] : W1[(64 + k) * 64 + (n - 64)];
  }

  // zero slice of g_agg / g_posupd (no sync needed; independent arrays)
  {
    float4 z = make_float4(0.f, 0.f, 0.f, 0.f);
    float4* ap = (float4*)(g_agg + (size_t)nb * kH);
#pragma unroll
    for (int q = 0; q < 2; q++) ap[tid + q * 256] = z;
    if (tid < 96) g_posupd[nb * kP + tid] = 0.f;
  }

  // prep for node nb + tid (threads 0..31)
  if (tid < 32) {
    int i = nb + tid;
    int b = i / kC, c = i - b * kC;
    float sx = 0.f, sy = 0.f, sz = 0.f, cnt = 0.f;
    unsigned bits = 0;
#pragma unroll
    for (int m = 0; m < kM; m++) {
      int idx = cni[c * kM + m];
      const float* p = positions + ((size_t)b * kC + idx) * kP;
      float x = p[0], y = p[1], z = p[2];
      g_npos[((size_t)i * kM + m) * 3 + 0] = x;
      g_npos[((size_t)i * kM + m) * 3 + 1] = y;
      g_npos[((size_t)i * kM + m) * 3 + 2] = z;
      g_np2[i * kM + m] = x * x + y * y + z * z;
      float mk = mask[c * kM + m];
      if (mk > 0.f) { bits |= (1u << m); sx += x; sy += y; sz += z; cnt += 1.f; }
    }
    float den = fmaxf(cnt, 1e-12f);
    g_cent[i * 3 + 0] = sx / den;
    g_cent[i * 3 + 1] = sy / den;
    g_cent[i * 3 + 2] = sz / den;
    if (b == 0) g_mbits[c] = bits;
  }
  __syncthreads();

  // featw: F = [f@W1a + b1 | f@W1b] for rows nb + rg*4 .. +4
  int rg = tid >> 5, cg = tid & 31;
  int row0 = nb + rg * 4;
  ull acc[4][2];
#pragma unroll
  for (int r = 0; r < 4; r++) { acc[r][0] = 0ull; acc[r][1] = 0ull; }
  const float* xp[4];
#pragma unroll
  for (int r = 0; r < 4; r++) xp[r] = features + (size_t)(row0 + r) * kH;
#pragma unroll
  for (int g = 0; g < 16; g++) {
    float4 xv[4];
#pragma unroll
    for (int r = 0; r < 4; r++) xv[r] = *(const float4*)(xp[r] + 4 * g);
#pragma unroll
    for (int kk = 0; kk < 4; kk++) {
      ulonglong2 w = *(const ulonglong2*)(sW + (4 * g + kk) * 128 + cg * 4);
#pragma unroll
      for (int r = 0; r < 4; r++) {
        ull d = dup2(((const float*)&xv[r])[kk]);
        ffma2(acc[r][0], d, w.x);
        ffma2(acc[r][1], d, w.y);
      }
    }
  }
  float4 bsel = make_float4(0.f, 0.f, 0.f, 0.f);
  if (cg < 16) bsel = *(const float4*)(b1 + cg * 4);
#pragma unroll
  for (int r = 0; r < 4; r++) {
    float2 v0 = unpack2(acc[r][0]);
    float2 v1 = unpack2(acc[r][1]);
    *(float4*)(g_fw + (size_t)(row0 + r) * 128 + cg * 4) =
        make_float4(v0.x + bsel.x, v0.y + bsel.y, v1.x + bsel.z,
                    v1.y + bsel.w);
  }
}

// msg_kernel: R12 structure (233us, spill-free at occupancy 3); b1 pre-folded
__global__ void __launch_bounds__(TBM, 3) msg_kernel(
    const float* __restrict__ features, const float* __restrict__ positions,
    const int* __restrict__ ei,
    const float* __restrict__ W1, const float* __restrict__ b1,
    const float* __restrict__ W2, const float* __restrict__ b2,
    const float* __restrict__ P1, const float* __restrict__ pb1,
    const float* __restrict__ P2, const float* __restrict__ pb2) {
  extern __shared__ float sm[];
  float* sW1c = sm + OFF_W1C;
  float* sW2 = sm + OFF_W2;
  float* sP1 = sm + OFF_P1;
  float* sP2 = sm + OFF_P2;
  float* sb2 = sm + OFF_B2;
  float* spb1 = sm + OFF_PB1;
  float* sHM = sm + OFF_HM;    // [128][68] H, then Msg
  float* sInv = sm + OFF_INV;  // [128][4]
  float* sRel = sm + OFF_REL;
  float* sWt = sm + OFF_WT;
  int* sDst = (int*)(sm + OFF_DST);
  int* sFs = (int*)(sm + OFF_FS);
  int* sFd = (int*)(sm + OFF_FD);

  int tid = threadIdx.x;
  for (int i = tid; i < 256; i += TBM) sW1c[i] = W1[128 * 64 + i];
  for (int i = tid; i < 64 * 64; i += TBM) { sW2[i] = W2[i]; sP1[i] = P1[i]; }
  if (tid < 64) { sP2[tid] = P2[tid]; sb2[tid] = b2[tid]; spb1[tid] = pb1[tid]; }
  float pb2v = pb2[0];

  // ---- gather (node indices + rel) ----
  if (tid < TILE) {
    int gr = blockIdx.x * TILE + tid;
    int b = gr / kE, e = gr - b * kE;
    int src = ei[e], dst = ei[kE + e];
    int is = b * kC + src, id = b * kC + dst;
    sFs[tid] = is;
    sFd[tid] = id;
    sDst[tid] = id;
    const float* ps = positions + (size_t)is * kP;
    const float* pd = positions + (size_t)id * kP;
    sRel[tid * 3 + 0] = ps[0] - pd[0];
    sRel[tid * 3 + 1] = ps[1] - pd[1];
    sRel[tid * 3 + 2] = ps[2] - pd[2];
  }
  __syncthreads();

  // ---- fused invariants: 2 threads per row ----
  {
    int row = tid >> 1, half = tid & 1;
    int is = sFs[row], id = sFd[row];
    unsigned mx = g_mbits[is >= kC ? is - kC : is];
    unsigned my = g_mbits[id >= kC ? id - kC : id];
    float dp[24], dp2[8];
    {
      const float4* a = (const float4*)(g_npos + (size_t)id * 24);
#pragma unroll
      for (int q = 0; q < 6; q++) ((float4*)dp)[q] = a[q];
      const float4* d2 = (const float4*)(g_np2 + (size_t)id * 8);
      ((float4*)dp2)[0] = d2[0];
      ((float4*)dp2)[1] = d2[1];
    }
    float sp[12], sp2[4];
    {
      const float4* a = (const float4*)(g_npos + (size_t)is * 24 + half * 12);
#pragma unroll
      for (int q = 0; q < 3; q++) ((float4*)sp)[q] = a[q];
      ((float4*)sp2)[0] = *(const float4*)(g_np2 + (size_t)is * 8 + half * 4);
    }
    float colmin[8];
#pragma unroll
    for (int n = 0; n < 8; n++) colmin[n] = 3.4e38f;
    float pairwise = 0.f, hxy = 0.f;
    unsigned mxs = mx >> (half * 4);
#pragma unroll
    for (int m = 0; m < 4; m++) {
      if ((mxs >> m) & 1) {
        float rowmin = 3.4e38f;
        float ax = sp[m * 3], ay = sp[m * 3 + 1], az = sp[m * 3 + 2],
              a2 = sp2[m];
#pragma unroll
        for (int n = 0; n < 8; n++) {
          if ((my >> n) & 1) {
            float s = a2 + dp2[n] -
                      2.f * (ax * dp[n * 3] + ay * dp[n * 3 + 1] +
                             az * dp[n * 3 + 2]);
            float d = sqrtf(fmaxf(s, 0.f) + 1e-12f);
            pairwise += d;
            rowmin = fminf(rowmin, d);
            colmin[n] = fminf(colmin[n], d);
          }
        }
        hxy = fmaxf(hxy, rowmin);
      }
    }
    pairwise += __shfl_xor_sync(0xffffffffu, pairwise, 1);
    hxy = fmaxf(hxy, __shfl_xor_sync(0xffffffffu, hxy, 1));
#pragma unroll
    for (int n = 0; n < 8; n++)
      colmin[n] = fminf(colmin[n], __shfl_xor_sync(0xffffffffu, colmin[n], 1));
    if (half == 0) {
      float hyx = 0.f;
#pragma unroll
      for (int n = 0; n < 8; n++)
        if ((my >> n) & 1) hyx = fmaxf(hyx, colmin[n]);
      float haus = fmaxf(hxy, hyx);
      float c0 = g_cent[is * 3 + 0] - g_cent[id * 3 + 0];
      float c1 = g_cent[is * 3 + 1] - g_cent[id * 3 + 1];
      float c2 = g_cent[is * 3 + 2] - g_cent[id * 3 + 2];
      float centroid = sqrtf(c0 * c0 + c1 * c1 + c2 * c2);
      float r0 = sRel[row * 3 + 0], r1 = sRel[row * 3 + 1],
            r2 = sRel[row * 3 + 2];
      float dist = sqrtf(r0 * r0 + r1 * r1 + r2 * r2);
      ((float4*)sInv)[row] = make_float4(dist, pairwise, centroid, haus);
    }
  }
  __syncthreads();

  int rg = tid >> 4, cg = tid & 15;
  int row0 = rg * 8;
  ull acc[8][2];

  // ---- GEMM1 (hoisted): acc = F[src](b1 folded) + F[dst] + inv@W1c ----
  {
#pragma unroll
    for (int r = 0; r < 8; r++) {
      int is = sFs[row0 + r], id = sFd[row0 + r];
      float4 fs = *(const float4*)(g_fw + (size_t)is * 128 + cg * 4);
      float4 fd = *(const float4*)(g_fw + (size_t)id * 128 + 64 + cg * 4);
      acc[r][0] = pack2f(fs.x + fd.x, fs.y + fd.y);
      acc[r][1] = pack2f(fs.z + fd.z, fs.w + fd.w);
    }
    float4 iv[8];
#pragma unroll
    for (int r = 0; r < 8; r++) iv[r] = ((const float4*)sInv)[row0 + r];
#pragma unroll
    for (int kk = 0; kk < 4; kk++) {
      ulonglong2 w = *(const ulonglong2*)(sW1c + kk * 64 + cg * 4);
#pragma unroll
      for (int r = 0; r < 8; r++) {
        ull d = dup2(((const float*)&iv[r])[kk]);
        ffma2(acc[r][0], d, w.x);
        ffma2(acc[r][1], d, w.y);
      }
    }
  }
#pragma unroll
  for (int i = 0; i < 8; i++)
#pragma unroll
    for (int p = 0; p < 2; p++) {
      float2 h = unpack2(acc[i][p]);
      h.x = silu_f(h.x);
      h.y = silu_f(h.y);
      *(float2*)(sHM + (row0 + i) * 68 + cg * 4 + 2 * p) = h;
    }
  __syncthreads();

  // ---- GEMM2: Msg = H @ W2 + b2 ----
#pragma unroll
  for (int i = 0; i < 8; i++) {
    acc[i][0] = *(const ull*)(sb2 + cg * 4 + 0);
    acc[i][1] = *(const ull*)(sb2 + cg * 4 + 2);
  }
  {
    const float* xp[8];
#pragma unroll
    for (int r = 0; r < 8; r++) xp[r] = sHM + (row0 + r) * 68;
    gemm64r<8>(xp, sW2, cg, acc);
  }
  __syncthreads();
#pragma unroll
  for (int i = 0; i < 8; i++)
#pragma unroll
    for (int p = 0; p < 2; p++) {
      float2 v = unpack2(acc[i][p]);
      *(float2*)(sHM + (row0 + i) * 68 + cg * 4 + 2 * p) = v;
    }
  __syncthreads();

  // ---- GEMM3: silu(Msg @ P1 + pb1) . P2, tanh -> wt ----
#pragma unroll
  for (int i = 0; i < 8; i++) {
    acc[i][0] = *(const ull*)(spb1 + cg * 4 + 0);
    acc[i][1] = *(const ull*)(spb1 + cg * 4 + 2);
  }
  {
    const float* xp[8];
#pragma unroll
    for (int r = 0; r < 8; r++) xp[r] = sHM + (row0 + r) * 68;
    gemm64r<8>(xp, sP1, cg, acc);
  }
  float part[8];
#pragma unroll
  for (int i = 0; i < 8; i++) {
    part[i] = 0.f;
#pragma unroll
    for (int p = 0; p < 2; p++) {
      float2 h = unpack2(acc[i][p]);
      part[i] = fmaf(silu_f(h.x), sP2[cg * 4 + 2 * p], part[i]);
      part[i] = fmaf(silu_f(h.y), sP2[cg * 4 + 2 * p + 1], part[i]);
    }
  }
#pragma unroll
  for (int i = 0; i < 8; i++) {
    float v = part[i];
    v += __shfl_xor_sync(0xffffffffu, v, 1);
    v += __shfl_xor_sync(0xffffffffu, v, 2);
    v += __shfl_xor_sync(0xffffffffu, v, 4);
    v += __shfl_xor_sync(0xffffffffu, v, 8);
    if (cg == 0) sWt[row0 + i] = tanhf(v + pb2v);
  }
  __syncthreads();

  // ---- scatter ----
  int lr = tid >> 1, ts = tid & 1;
  int ob = sDst[lr];
  float* ap = g_agg + (size_t)ob * kH + ts * 32;
  const float* mp = sHM + lr * 68 + ts * 32;
#pragma unroll
  for (int q = 0; q < 8; q++)
    red_add_v4(ap + q * 4, mp[q * 4 + 0], mp[q * 4 + 1], mp[q * 4 + 2],
               mp[q * 4 + 3]);
  if (ts == 0) {
    float w = sWt[lr];
    float* pp = g_posupd + (size_t)ob * kP;
    atomicAdd(pp + 0, w * sRel[lr * 3 + 0]);
    atomicAdd(pp + 1, w * sRel[lr * 3 + 1]);
    atomicAdd(pp + 2, w * sRel[lr * 3 + 2]);
  }
}

__global__ void __launch_bounds__(TB, 2) node_kernel(
    const float* __restrict__ features, const float* __restrict__ positions,
    const float* __restrict__ degree,
    const float* __restrict__ U1, const float* __restrict__ ub1,
    const float* __restrict__ U2, const float* __restrict__ ub2,
    float* __restrict__ out_feat, float* __restrict__ out_pos) {
  extern __shared__ float smf[];
  float* sU1 = smf + NOFF_U1;
  float* sU2 = smf + NOFF_U2;
  float* sub1 = smf + NOFF_UB1;
  float* sub2 = smf + NOFF_UB2;
  float* sHM = smf + NOFF_HM;  // [160][68]
  float* sInvD = smf + NOFF_IDG;

  int tid = threadIdx.x;
  for (int i = tid; i < 128 * 64; i += TB) sU1[i] = U1[i];
  for (int i = tid; i < 64 * 64; i += TB) sU2[i] = U2[i];
  if (tid < 64) { sub1[tid] = ub1[tid]; sub2[tid] = ub2[tid]; }

  if (tid < NTILE) {
    int gr = blockIdx.x * NTILE + tid;
    int c = gr % kC;
    sInvD[tid] = 1.f / fmaxf(degree[c], 1.f);
  }
  // fused pos update: block b owns pos elements [480b, 480b+480)
  if (tid < 480) {
    int pi = blockIdx.x * 480 + tid;
    out_pos[pi] = positions[pi] + g_posupd[pi];
  }
  __syncthreads();

  int rg = tid >> 4, cg = tid & 15;
  int row0 = rg * 5;
  int gr0 = blockIdx.x * NTILE + row0;

  ull acc[5][2];
#pragma unroll
  for (int i = 0; i < 5; i++) { acc[i][0] = 0ull; acc[i][1] = 0ull; }

  {
    const float* xp[5];
#pragma unroll
    for (int r = 0; r < 5; r++) xp[r] = g_agg + (size_t)(gr0 + r) * kH;
    gemm64r<5>(xp, sU1 + 64 * 64, cg, acc);
  }
  {
    ull bias0 = *(const ull*)(sub1 + cg * 4 + 0);
    ull bias1 = *(const ull*)(sub1 + cg * 4 + 2);
#pragma unroll
    for (int i = 0; i < 5; i++) {
      ull dv = dup2(sInvD[row0 + i]);
      fma2_scale_bias(acc[i][0], dv, bias0);
      fma2_scale_bias(acc[i][1], dv, bias1);
    }
  }
  {
    const float* xp[5];
#pragma unroll
    for (int r = 0; r < 5; r++) xp[r] = features + (size_t)(gr0 + r) * kH;
    gemm64r<5>(xp, sU1, cg, acc);
  }
#pragma unroll
  for (int i = 0; i < 5; i++)
#pragma unroll
    for (int p = 0; p < 2; p++) {
      float2 h = unpack2(acc[i][p]);
      h.x = silu_f(h.x);
      h.y = silu_f(h.y);
      *(float2*)(sHM + (row0 + i) * 68 + cg * 4 + 2 * p) = h;
    }
  __syncthreads();

#pragma unroll
  for (int i = 0; i < 5; i++) {
    acc[i][0] = *(const ull*)(sub2 + cg * 4 + 0);
    acc[i][1] = *(const ull*)(sub2 + cg * 4 + 2);
  }
  {
    const float* xp[5];
#pragma unroll
    for (int r = 0; r < 5; r++) xp[r] = sHM + (row0 + r) * 68;
    gemm64r<5>(xp, sU2, cg, acc);
  }
#pragma unroll
  for (int i = 0; i < 5; i++) {
    int g2 = gr0 + i;
    const float4 f = ((const float4*)(features + (size_t)g2 * kH))[cg];
    float2 v0 = unpack2(acc[i][0]);
    float2 v1 = unpack2(acc[i][1]);
    float4 o;
    o.x = f.x + v0.x;
    o.y = f.y + v0.y;
    o.z = f.z + v1.x;
    o.w = f.w + v1.y;
    ((float4*)(out_feat + (size_t)g2 * kH))[cg] = o;
  }
}

extern "C" void kernel_launch(void* const* d_in, const int* in_sizes, int n_in,
                              void* d_out, int out_size) {
  const float* features = (const float*)d_in[0];
  const float* positions = (const float*)d_in[1];
  const int* edge_index = (const int*)d_in[2];
  const float* degree = (const float*)d_in[3];
  const int* cni = (const int*)d_in[4];
  const float* mask = (const float*)d_in[5];
  const float* W1 = (const float*)d_in[6];
  const float* b1 = (const float*)d_in[7];
  const float* W2 = (const float*)d_in[8];
  const float* b2 = (const float*)d_in[9];
  const float* P1 = (const float*)d_in[10];
  const float* pb1 = (const float*)d_in[11];
  const float* P2 = (const float*)d_in[12];
  const float* pb2 = (const float*)d_in[13];
  const float* U1 = (const float*)d_in[14];
  const float* ub1 = (const float*)d_in[15];
  const float* U2 = (const float*)d_in[16];
  const float* ub2 = (const float*)d_in[17];

  float* out_feat = (float*)d_out;
  float* out_pos = out_feat + (size_t)kNC * kH;

  size_t msg_smem = (size_t)MSG_SMEM_FLOATS * sizeof(float);    // 75,264 B
  size_t node_smem = (size_t)NODE_SMEM_FLOATS * sizeof(float);  // 93,824 B
  cudaFuncSetAttribute(msg_kernel, cudaFuncAttributeMaxDynamicSharedMemorySize,
                       (int)msg_smem);
  cudaFuncSetAttribute(node_kernel, cudaFuncAttributeMaxDynamicSharedMemorySize,
                       (int)node_smem);

  prepfw_kernel<<<kNC / 32, 256>>>(features, W1, b1, positions, cni, mask);
  msg_kernel<<<kNR / TILE, TBM, msg_smem>>>(features, positions, edge_index, W1,
                                            b1, W2, b2, P1, pb1, P2, pb2);
  node_kernel<<<kNC / NTILE, TB, node_smem>>>(features, positions, degree, U1,
                                              ub1, U2, ub2, out_feat, out_pos);
}